// round 9
// baseline (speedup 1.0000x reference)
#include <cuda_runtime.h>
#include <cuda_bf16.h>
#include <math.h>
#include <stdint.h>

#define BB 32
#define DD 1024
#define TT 1000
#define TP 1024
#define VV 80
#define NTB 96
#define LMAX 200
#define BLANK 79
#define NEGV (-1e30f)

#if defined(__CUDA_ARCH_FEAT_SM103_ALL) || defined(__CUDA_ARCH_FEAT_SM100_ALL)
#define HAS_TCGEN05 1
#else
#define HAS_TCGEN05 0
#endif

// ---------------- scratch ----------------------------------------------------
__device__ __nv_bfloat16 g_xh[(size_t)BB * TP * DD];
__device__ __nv_bfloat16 g_xl[(size_t)BB * TP * DD];
__device__ __nv_bfloat16 g_w1h[(size_t)DD * DD];
__device__ __nv_bfloat16 g_w1l[(size_t)DD * DD];
__device__ __nv_bfloat16 g_w2h[(size_t)NTB * DD];
__device__ __nv_bfloat16 g_w2l[(size_t)NTB * DD];
__device__ __nv_bfloat16 g_hh[(size_t)BB * TP * DD];
__device__ __nv_bfloat16 g_hl[(size_t)BB * TP * DD];
__device__ float         g_lp[(size_t)BB * TT * VV];
__device__ float         g_loss[BB];

// ---------------- PTX helpers ------------------------------------------------
__device__ __forceinline__ uint32_t sm_u32(const void* p) {
    uint32_t a;
    asm("{ .reg .u64 t; cvta.to.shared.u64 t, %1; cvt.u32.u64 %0, t; }"
        : "=r"(a) : "l"(p));
    return a;
}
__device__ __forceinline__ bool elect1() {
    uint32_t p;
    asm volatile("{ .reg .pred p; elect.sync _|p, 0xFFFFFFFF; selp.b32 %0,1,0,p; }"
                 : "=r"(p));
    return p != 0;
}
__device__ __forceinline__ uint32_t swz(uint32_t off) { return off ^ ((off >> 3) & 0x70u); }
__device__ __forceinline__ uint64_t mkdesc(uint32_t addr) {
    const uint64_t base = (2ull << 61) | (1ull << 46) | (64ull << 32) | (1ull << 16);
    return base | (uint64_t)((addr >> 4) & 0x3FFF);
}
__device__ __forceinline__ void cp16(uint32_t dst, const void* src) {
    asm volatile("cp.async.cg.shared.global [%0], [%1], 16;" :: "r"(dst), "l"(src));
}
#define CP_COMMIT() asm volatile("cp.async.commit_group;" ::: "memory")
__device__ __forceinline__ void mbar_wait(uint32_t mbar, uint32_t parity) {
    asm volatile(
        "{\n\t.reg .pred P;\n\t"
        "WL%=:\n\t"
        "mbarrier.try_wait.parity.acquire.cta.shared::cta.b64 P, [%0], %1;\n\t"
        "@!P bra WL%=;\n\t}"
        :: "r"(mbar), "r"(parity) : "memory");
}

#if HAS_TCGEN05
__device__ __forceinline__ void mma_bf16_ss(uint32_t d, uint64_t ad, uint64_t bd,
                                            uint32_t idesc, bool acc) {
    uint32_t en = acc ? 1u : 0u;
    asm volatile(
        "{\n\t.reg .pred p;\n\t"
        "setp.ne.u32 p, %5, 0;\n\t"
        "tcgen05.mma.cta_group::1.kind::f16 [%0], %1, %2, %3, {%4,%4,%4,%4}, p;\n\t}"
        :: "r"(d), "l"(ad), "l"(bd), "r"(idesc), "r"(0u), "r"(en) : "memory");
}
#define LDTM_X32(r, a) asm volatile( \
    "tcgen05.ld.sync.aligned.32x32b.x32.b32 " \
    "{%0,%1,%2,%3,%4,%5,%6,%7,%8,%9,%10,%11,%12,%13,%14,%15," \
    "%16,%17,%18,%19,%20,%21,%22,%23,%24,%25,%26,%27,%28,%29,%30,%31}, [%32];" \
    : "=r"((r)[0]),"=r"((r)[1]),"=r"((r)[2]),"=r"((r)[3]), \
      "=r"((r)[4]),"=r"((r)[5]),"=r"((r)[6]),"=r"((r)[7]), \
      "=r"((r)[8]),"=r"((r)[9]),"=r"((r)[10]),"=r"((r)[11]), \
      "=r"((r)[12]),"=r"((r)[13]),"=r"((r)[14]),"=r"((r)[15]), \
      "=r"((r)[16]),"=r"((r)[17]),"=r"((r)[18]),"=r"((r)[19]), \
      "=r"((r)[20]),"=r"((r)[21]),"=r"((r)[22]),"=r"((r)[23]), \
      "=r"((r)[24]),"=r"((r)[25]),"=r"((r)[26]),"=r"((r)[27]), \
      "=r"((r)[28]),"=r"((r)[29]),"=r"((r)[30]),"=r"((r)[31]) \
    : "r"(a))
#define LDTM_X16(r, a) asm volatile( \
    "tcgen05.ld.sync.aligned.32x32b.x16.b32 " \
    "{%0,%1,%2,%3,%4,%5,%6,%7,%8,%9,%10,%11,%12,%13,%14,%15}, [%16];" \
    : "=r"((r)[0]),"=r"((r)[1]),"=r"((r)[2]),"=r"((r)[3]), \
      "=r"((r)[4]),"=r"((r)[5]),"=r"((r)[6]),"=r"((r)[7]), \
      "=r"((r)[8]),"=r"((r)[9]),"=r"((r)[10]),"=r"((r)[11]), \
      "=r"((r)[12]),"=r"((r)[13]),"=r"((r)[14]),"=r"((r)[15]) \
    : "r"(a))
#define TM_WAIT_LD() asm volatile("tcgen05.wait::ld.sync.aligned;" ::: "memory")
#endif

// ---------------- pre-passes -------------------------------------------------
__global__ __launch_bounds__(256) void k_prep_dec(const float* __restrict__ dec) {
    __shared__ float s[32][33];
    const int b = blockIdx.z, t0 = blockIdx.x * 32, d0 = blockIdx.y * 32;
    const int tx = threadIdx.x, ty = threadIdx.y;
    const float* in = dec + (size_t)b * DD * TT;
#pragma unroll
    for (int i = 0; i < 4; i++) {
        int d = d0 + ty + 8 * i, t = t0 + tx;
        s[ty + 8 * i][tx] = (t < TT) ? in[(size_t)d * TT + t] : 0.f;
    }
    __syncthreads();
#pragma unroll
    for (int i = 0; i < 4; i++) {
        int t = t0 + ty + 8 * i, d = d0 + tx;
        float v = s[tx][ty + 8 * i];
        __nv_bfloat16 hi = __float2bfloat16_rn(v);
        __nv_bfloat16 lo = __float2bfloat16_rn(v - __bfloat162float(hi));
        size_t idx = (size_t)b * TP * DD + (size_t)t * DD + d;
        g_xh[idx] = hi;
        g_xl[idx] = lo;
    }
}
__global__ __launch_bounds__(256) void k_prep_w1(const float* __restrict__ W1) {
    __shared__ float s[32][33];
    const int e0 = blockIdx.x * 32, d0 = blockIdx.y * 32;
    const int tx = threadIdx.x, ty = threadIdx.y;
#pragma unroll
    for (int i = 0; i < 4; i++)
        s[ty + 8 * i][tx] = W1[(size_t)(d0 + ty + 8 * i) * DD + e0 + tx];
    __syncthreads();
#pragma unroll
    for (int i = 0; i < 4; i++) {
        float v = s[tx][ty + 8 * i];
        __nv_bfloat16 hi = __float2bfloat16_rn(v);
        __nv_bfloat16 lo = __float2bfloat16_rn(v - __bfloat162float(hi));
        size_t idx = (size_t)(e0 + ty + 8 * i) * DD + d0 + tx;
        g_w1h[idx] = hi;
        g_w1l[idx] = lo;
    }
}
__global__ __launch_bounds__(256) void k_prep_w2(const float* __restrict__ W2) {
    int idx = blockIdx.x * 256 + threadIdx.x;
    if (idx < NTB * DD) {
        int v = idx / DD, d = idx - v * DD;
        float x = (v < VV) ? W2[(size_t)d * VV + v] : 0.f;
        __nv_bfloat16 hi = __float2bfloat16_rn(x);
        __nv_bfloat16 lo = __float2bfloat16_rn(x - __bfloat162float(hi));
        g_w2h[idx] = hi;
        g_w2l[idx] = lo;
    }
}

// ---------------- GEMM1: N-tile 256, split-bf16, lag-1, dual mbarrier --------
__global__ __launch_bounds__(256) void k_gemm1(const float* __restrict__ dec,
                                               const float* __restrict__ W1,
                                               const float* __restrict__ b1) {
    const int tid = threadIdx.x;
    const int b = blockIdx.z, m0 = blockIdx.x * 128, n0 = blockIdx.y * 256;

#if HAS_TCGEN05
    constexpr int ASZ = 16384;           // 128 rows x 128B
    constexpr int BSZ = 32768;           // 256 rows x 128B
    constexpr int STAGE = 2 * ASZ + 2 * BSZ;  // 98304
    constexpr int NKB = DD / 64;         // 16
    extern __shared__ char dyn_raw[];
    __shared__ uint32_t s_tmem;
    __shared__ __align__(16) uint64_t s_mbar[2];

    const int wid = tid >> 5, lid = tid & 31;
    const uint32_t raw = sm_u32(dyn_raw);
    const uint32_t sb = (raw + 1023u) & ~1023u;
    char* dynsm = dyn_raw + (sb - raw);

    if (wid == 0) {
        asm volatile("tcgen05.alloc.cta_group::1.sync.aligned.shared::cta.b32 [%0], %1;"
                     :: "r"(sm_u32(&s_tmem)), "r"(256u) : "memory");
        asm volatile("tcgen05.relinquish_alloc_permit.cta_group::1.sync.aligned;");
        if (elect1()) {
            asm volatile("mbarrier.init.shared.b64 [%0], 1;"
                         :: "r"(sm_u32(&s_mbar[0])) : "memory");
            asm volatile("mbarrier.init.shared.b64 [%0], 1;"
                         :: "r"(sm_u32(&s_mbar[1])) : "memory");
        }
    }
    __syncthreads();
    const uint32_t tmem = s_tmem;
    const uint32_t mb0 = sm_u32(&s_mbar[0]);
    const uint32_t mb1 = sm_u32(&s_mbar[1]);

    const __nv_bfloat16* Ah = g_xh + (size_t)b * TP * DD + (size_t)m0 * DD;
    const __nv_bfloat16* Al = g_xl + (size_t)b * TP * DD + (size_t)m0 * DD;
    const __nv_bfloat16* Bh = g_w1h + (size_t)n0 * DD;
    const __nv_bfloat16* Bl = g_w1l + (size_t)n0 * DD;

    auto ldstage = [&](int st, int kb) {
        const int k0 = kb * 64;
        const uint32_t su = sb + st * STAGE;
#pragma unroll
        for (int i = 0; i < 24; i++) {
            int c = tid + i * 256;   // 0..6143 (16B chunks)
            uint32_t dst;
            const __nv_bfloat16* src;
            if (c < 1024) {
                int r = c >> 3, ch = c & 7;
                dst = su + swz((uint32_t)(r * 128 + ch * 16));
                src = Ah + (size_t)r * DD + k0 + ch * 8;
            } else if (c < 2048) {
                int cc = c - 1024, r = cc >> 3, ch = cc & 7;
                dst = su + ASZ + swz((uint32_t)(r * 128 + ch * 16));
                src = Al + (size_t)r * DD + k0 + ch * 8;
            } else if (c < 4096) {
                int cc = c - 2048, r = cc >> 3, ch = cc & 7;   // r 0..255
                dst = su + 2 * ASZ + swz((uint32_t)(r * 128 + ch * 16));
                src = Bh + (size_t)r * DD + k0 + ch * 8;
            } else {
                int cc = c - 4096, r = cc >> 3, ch = cc & 7;
                dst = su + 2 * ASZ + BSZ + swz((uint32_t)(r * 128 + ch * 16));
                src = Bl + (size_t)r * DD + k0 + ch * 8;
            }
            cp16(dst, src);
        }
    };

    ldstage(0, 0);
    CP_COMMIT();

    const uint32_t idesc = (1u << 4) | (1u << 7) | (1u << 10) |
                           (16u << 17) | (8u << 24);   // N=128, M=128

    for (int kb = 0; kb < NKB; kb++) {
        const int st = kb & 1;
        asm volatile("cp.async.wait_group 0;" ::: "memory");
        __syncthreads();
        if (wid == 0) {
            asm volatile("fence.proxy.async.shared::cta;" ::: "memory");
            if (elect1()) {
                const uint32_t su = sb + st * STAGE;
                uint64_t ah  = mkdesc(su);
                uint64_t al  = mkdesc(su + ASZ);
                uint64_t bh0 = mkdesc(su + 2 * ASZ);
                uint64_t bh1 = mkdesc(su + 2 * ASZ + ASZ);       // rows 128..255
                uint64_t bl0 = mkdesc(su + 2 * ASZ + BSZ);
                uint64_t bl1 = mkdesc(su + 2 * ASZ + BSZ + ASZ);
#pragma unroll
                for (int s4 = 0; s4 < 4; s4++) {
                    uint64_t o = 2 * s4;
                    bool first = (kb == 0 && s4 == 0);
                    mma_bf16_ss(tmem,       ah + o, bh0 + o, idesc, !first);
                    mma_bf16_ss(tmem,       ah + o, bl0 + o, idesc, true);
                    mma_bf16_ss(tmem,       al + o, bh0 + o, idesc, true);
                    mma_bf16_ss(tmem + 128, ah + o, bh1 + o, idesc, !first);
                    mma_bf16_ss(tmem + 128, ah + o, bl1 + o, idesc, true);
                    mma_bf16_ss(tmem + 128, al + o, bh1 + o, idesc, true);
                }
                // commit kb -> mbar[kb&1]; phase index on that barrier = kb>>1
                asm volatile(
                    "tcgen05.commit.cta_group::1.mbarrier::arrive::one.shared::cluster.b64 [%0];"
                    :: "r"(st ? mb1 : mb0) : "memory");
            }
        }
        if (kb + 1 < NKB) {
            if (kb >= 1) {
                // wait for commit kb-1 on mbar[(kb-1)&1], parity ((kb-1)>>1)&1
                int pk = kb - 1;
                mbar_wait((pk & 1) ? mb1 : mb0, (uint32_t)((pk >> 1) & 1));
            }
            ldstage(st ^ 1, kb + 1);
            CP_COMMIT();
        }
    }
    {
        int pk = NKB - 1;
        mbar_wait((pk & 1) ? mb1 : mb0, (uint32_t)((pk >> 1) & 1));
    }

    asm volatile("tcgen05.fence::after_thread_sync;" ::: "memory");
    __syncthreads();

    // epilogue: TMEM(256 cols) -> smem fp32 -> bias+relu -> split bf16 hi/lo
    float* sh = (float*)dynsm;  // stride 261 floats, 128 rows (133.6KB)
    if (wid < 4) {
        const int row = wid * 32 + lid;
#pragma unroll
        for (int c4 = 0; c4 < 8; c4++) {
            uint32_t r[32];
            LDTM_X32(r, tmem + c4 * 32);
            TM_WAIT_LD();
#pragma unroll
            for (int j = 0; j < 32; j++)
                sh[row * 261 + c4 * 32 + j] = __uint_as_float(r[j]);
        }
        asm volatile("tcgen05.fence::before_thread_sync;" ::: "memory");
    }
    __syncthreads();
#pragma unroll 4
    for (int i = 0; i < 64; i++) {
        int idx = tid + i * 256;               // pair idx over 128x128
        int r = idx >> 7, cp2 = (idx & 127) * 2;
        float v0 = fmaxf(sh[r * 261 + cp2] + b1[n0 + cp2], 0.f);
        float v1 = fmaxf(sh[r * 261 + cp2 + 1] + b1[n0 + cp2 + 1], 0.f);
        __nv_bfloat16 h0 = __float2bfloat16_rn(v0);
        __nv_bfloat16 h1 = __float2bfloat16_rn(v1);
        __nv_bfloat16 l0 = __float2bfloat16_rn(v0 - __bfloat162float(h0));
        __nv_bfloat16 l1 = __float2bfloat16_rn(v1 - __bfloat162float(h1));
        size_t off = ((size_t)b * TP + m0 + r) * DD + n0 + cp2;
        *reinterpret_cast<__nv_bfloat162*>(&g_hh[off]) = __nv_bfloat162(h0, h1);
        *reinterpret_cast<__nv_bfloat162*>(&g_hl[off]) = __nv_bfloat162(l0, l1);
    }
    __syncthreads();
    if (wid == 0)
        asm volatile("tcgen05.dealloc.cta_group::1.sync.aligned.b32 %0, %1;"
                     :: "r"(tmem), "r"(256u));

#else  // SIMT fallback (compile-only on non-103a pass)
    __shared__ float As[16][128];
    __shared__ float Bs[16][128];
    const int tx = tid & 15, ty = tid >> 4;
    const float* A = dec + (size_t)b * DD * TT;
    for (int nh = 0; nh < 2; nh++) {
        const int n0h = n0 + nh * 128;
        float acc[8][8];
#pragma unroll
        for (int i = 0; i < 8; i++)
#pragma unroll
            for (int j = 0; j < 8; j++) acc[i][j] = 0.f;
        for (int k0 = 0; k0 < DD; k0 += 16) {
            __syncthreads();
#pragma unroll
            for (int i = 0; i < 8; i++) {
                int idx = tid + i * 256;
                int kk = idx >> 7, mm = idx & 127;
                int m = m0 + mm;
                As[kk][mm] = (m < TT) ? A[(size_t)(k0 + kk) * TT + m] : 0.f;
                Bs[kk][mm] = W1[(size_t)(k0 + kk) * DD + n0h + mm];
            }
            __syncthreads();
#pragma unroll
            for (int kk = 0; kk < 16; kk++) {
                float a[8], w[8];
#pragma unroll
                for (int i = 0; i < 8; i++) a[i] = As[kk][ty * 8 + i];
#pragma unroll
                for (int j = 0; j < 8; j++) w[j] = Bs[kk][tx * 8 + j];
#pragma unroll
                for (int i = 0; i < 8; i++)
#pragma unroll
                    for (int j = 0; j < 8; j++) acc[i][j] = fmaf(a[i], w[j], acc[i][j]);
            }
        }
#pragma unroll
        for (int i = 0; i < 8; i++) {
            int m = m0 + ty * 8 + i;
#pragma unroll
            for (int j = 0; j < 8; j++) {
                int n = n0h + tx * 8 + j;
                float v = fmaxf(acc[i][j] + b1[n], 0.f);
                __nv_bfloat16 hi = __float2bfloat16_rn(v);
                size_t off = ((size_t)b * TP + m) * DD + n;
                g_hh[off] = hi;
                g_hl[off] = __float2bfloat16_rn(v - __bfloat162float(hi));
            }
        }
        __syncthreads();
    }
#endif
}

// ---------------- GEMM2 + fused softmax, lag-1, dual mbarrier ----------------
__global__ __launch_bounds__(256) void k_gemm2(const float* __restrict__ b2) {
    const int tid = threadIdx.x;
    const int b = blockIdx.y, m0 = blockIdx.x * 128;

#if HAS_TCGEN05
    constexpr int ASZ = 16384;
    constexpr int BSZ = NTB * 128;            // 12288
    constexpr int STAGE = 2 * ASZ + 2 * BSZ;  // 57344
    constexpr int NKB = DD / 64;
    extern __shared__ char dyn_raw[];
    __shared__ uint32_t s_tmem;
    __shared__ __align__(16) uint64_t s_mbar[2];

    const int wid = tid >> 5, lid = tid & 31;
    const uint32_t raw = sm_u32(dyn_raw);
    const uint32_t sb = (raw + 1023u) & ~1023u;
    char* dynsm = dyn_raw + (sb - raw);

    if (wid == 0) {
        asm volatile("tcgen05.alloc.cta_group::1.sync.aligned.shared::cta.b32 [%0], %1;"
                     :: "r"(sm_u32(&s_tmem)), "r"(128u) : "memory");
        asm volatile("tcgen05.relinquish_alloc_permit.cta_group::1.sync.aligned;");
        if (elect1()) {
            asm volatile("mbarrier.init.shared.b64 [%0], 1;"
                         :: "r"(sm_u32(&s_mbar[0])) : "memory");
            asm volatile("mbarrier.init.shared.b64 [%0], 1;"
                         :: "r"(sm_u32(&s_mbar[1])) : "memory");
        }
    }
    __syncthreads();
    const uint32_t tmem = s_tmem;
    const uint32_t mb0 = sm_u32(&s_mbar[0]);
    const uint32_t mb1 = sm_u32(&s_mbar[1]);

    const __nv_bfloat16* Ah = g_hh + (size_t)b * TP * DD + (size_t)m0 * DD;
    const __nv_bfloat16* Al = g_hl + (size_t)b * TP * DD + (size_t)m0 * DD;

    auto ldstage = [&](int st, int kb) {
        const int k0 = kb * 64;
        const uint32_t su = sb + st * STAGE;
#pragma unroll
        for (int i = 0; i < 14; i++) {
            int c = tid + i * 256;
            uint32_t dst;
            const __nv_bfloat16* src;
            if (c < 1024) {
                int r = c >> 3, ch = c & 7;
                dst = su + swz((uint32_t)(r * 128 + ch * 16));
                src = Ah + (size_t)r * DD + k0 + ch * 8;
            } else if (c < 2048) {
                int cc = c - 1024, r = cc >> 3, ch = cc & 7;
                dst = su + ASZ + swz((uint32_t)(r * 128 + ch * 16));
                src = Al + (size_t)r * DD + k0 + ch * 8;
            } else if (c < 2816) {
                int cc = c - 2048, r = cc >> 3, ch = cc & 7;
                dst = su + 2 * ASZ + swz((uint32_t)(r * 128 + ch * 16));
                src = g_w2h + (size_t)r * DD + k0 + ch * 8;
            } else {
                int cc = c - 2816, r = cc >> 3, ch = cc & 7;
                dst = su + 2 * ASZ + BSZ + swz((uint32_t)(r * 128 + ch * 16));
                src = g_w2l + (size_t)r * DD + k0 + ch * 8;
            }
            cp16(dst, src);
        }
    };

    ldstage(0, 0);
    CP_COMMIT();

    const uint32_t idesc = (1u << 4) | (1u << 7) | (1u << 10) |
                           ((uint32_t)(NTB / 8) << 17) | (8u << 24);

    for (int kb = 0; kb < NKB; kb++) {
        const int st = kb & 1;
        asm volatile("cp.async.wait_group 0;" ::: "memory");
        __syncthreads();
        if (wid == 0) {
            asm volatile("fence.proxy.async.shared::cta;" ::: "memory");
            if (elect1()) {
                const uint32_t su = sb + st * STAGE;
                uint64_t ah = mkdesc(su);
                uint64_t al = mkdesc(su + ASZ);
                uint64_t bh = mkdesc(su + 2 * ASZ);
                uint64_t bl = mkdesc(su + 2 * ASZ + BSZ);
#pragma unroll
                for (int s4 = 0; s4 < 4; s4++) {
                    uint64_t o = 2 * s4;
                    mma_bf16_ss(tmem, ah + o, bh + o, idesc, !(kb == 0 && s4 == 0));
                    mma_bf16_ss(tmem, ah + o, bl + o, idesc, true);
                    mma_bf16_ss(tmem, al + o, bh + o, idesc, true);
                }
                asm volatile(
                    "tcgen05.commit.cta_group::1.mbarrier::arrive::one.shared::cluster.b64 [%0];"
                    :: "r"(st ? mb1 : mb0) : "memory");
            }
        }
        if (kb + 1 < NKB) {
            if (kb >= 1) {
                int pk = kb - 1;
                mbar_wait((pk & 1) ? mb1 : mb0, (uint32_t)((pk >> 1) & 1));
            }
            ldstage(st ^ 1, kb + 1);
            CP_COMMIT();
        }
    }
    {
        int pk = NKB - 1;
        mbar_wait((pk & 1) ? mb1 : mb0, (uint32_t)((pk >> 1) & 1));
    }

    asm volatile("tcgen05.fence::after_thread_sync;" ::: "memory");
    __syncthreads();

    float* sh = (float*)dynsm;  // [128][81]
    if (wid < 4) {
        float v[VV];
        {
            uint32_t r[32];
            LDTM_X32(r, tmem);
            TM_WAIT_LD();
#pragma unroll
            for (int j = 0; j < 32; j++) v[j] = __uint_as_float(r[j]);
        }
        {
            uint32_t r[32];
            LDTM_X32(r, tmem + 32);
            TM_WAIT_LD();
#pragma unroll
            for (int j = 0; j < 32; j++) v[32 + j] = __uint_as_float(r[j]);
        }
        {
            uint32_t r[16];
            LDTM_X16(r, tmem + 64);
            TM_WAIT_LD();
#pragma unroll
            for (int j = 0; j < 16; j++) v[64 + j] = __uint_as_float(r[j]);
        }
        asm volatile("tcgen05.fence::before_thread_sync;" ::: "memory");
        float mx = -1e30f;
#pragma unroll
        for (int j = 0; j < VV; j++) { v[j] += b2[j]; mx = fmaxf(mx, v[j]); }
        float sum = 0.f;
#pragma unroll
        for (int j = 0; j < VV; j++) sum += expf(v[j] - mx);
        const float lse = mx + logf(sum);
        const int row = wid * 32 + lid;
#pragma unroll
        for (int j = 0; j < VV; j++) sh[row * 81 + j] = v[j] - lse;
    }
    __syncthreads();
#pragma unroll 4
    for (int i = 0; i < 40; i++) {
        int idx = tid + i * 256;
        int rr = idx / 80, cc = idx - rr * 80;
        int t = m0 + rr;
        if (t < TT) g_lp[((size_t)b * TT + t) * VV + cc] = sh[rr * 81 + cc];
    }
    __syncthreads();
    if (wid == 0)
        asm volatile("tcgen05.dealloc.cta_group::1.sync.aligned.b32 %0, %1;"
                     :: "r"(tmem), "r"(128u));

#else  // SIMT fallback (compile-only)
    const int r = m0 + (tid & 127);
    if (tid < 128) {
        float v[VV];
        for (int j = 0; j < VV; j++) v[j] = b2[j];
        const __nv_bfloat16* hh = g_hh + ((size_t)b * TP + r) * DD;
        const __nv_bfloat16* hl = g_hl + ((size_t)b * TP + r) * DD;
        for (int k = 0; k < DD; k++) {
            float hv = __bfloat162float(hh[k]) + __bfloat162float(hl[k]);
            for (int j = 0; j < VV; j++)
                v[j] = fmaf(hv, __bfloat162float(g_w2h[(size_t)j * DD + k]) +
                                 __bfloat162float(g_w2l[(size_t)j * DD + k]), v[j]);
        }
        float mx = -1e30f;
        for (int j = 0; j < VV; j++) mx = fmaxf(mx, v[j]);
        float sum = 0.f;
        for (int j = 0; j < VV; j++) sum += expf(v[j] - mx);
        float lse = mx + logf(sum);
        if (r < TT)
            for (int j = 0; j < VV; j++)
                g_lp[((size_t)b * TT + r) * VV + j] = v[j] - lse;
    }
#endif
}

// ---------------- CTC DP: median-trick lse3 + early-exit + reg prefetch ------
__global__ __launch_bounds__(448) void k_ctc(const int* __restrict__ tgt,
                                             const int* __restrict__ dlen,
                                             const int* __restrict__ tlen) {
    const int b = blockIdx.x;
    const int L = tlen[b];
    const int S = 2 * L + 1;
    const int len = dlen[b];
    const int s = threadIdx.x;

    if (s >= ((S + 31) & ~31)) return;  // retire unused warps entirely

    __shared__ float A[2][2 * LMAX + 1];
    __shared__ int ext[2 * LMAX + 1];

    const float* lpb = g_lp + (size_t)b * TT * VV;

    int lbl = BLANK;
    if (s < S) {
        lbl = (s & 1) ? tgt[b * LMAX + (s >> 1)] : BLANK;
        ext[s] = lbl;
    }
    __syncthreads();
    bool sk = false;
    if (s < S) {
        sk = ((s & 1) && s >= 3 && lbl != ext[s - 2]);
        float a0 = NEGV;
        if (s == 0)      a0 = lpb[BLANK];
        else if (s == 1) a0 = lpb[lbl];
        A[0][s] = a0;
    }

    float eA = 0.f, eB = 0.f;
    if (s < S) {
        int t1 = (1 < len) ? 1 : len - 1;
        int t2 = (2 < len) ? 2 : len - 1;
        eA = lpb[(size_t)t1 * VV + lbl];
        eB = lpb[(size_t)t2 * VV + lbl];
    }
    __syncthreads();

    for (int t = 1; t < len; t++) {
        const int cur = t & 1, prev = cur ^ 1;
        float e_cur = eA;
        eA = eB;
        if (s < S) {
            int tn = (t + 2 < len) ? t + 2 : len - 1;
            eB = lpb[(size_t)tn * VV + lbl];
            float a  = A[prev][s];
            float bv = (s >= 1) ? A[prev][s - 1] : NEGV;
            float cv = sk ? A[prev][s - 2] : NEGV;
            float mx = fmaxf(a, fmaxf(bv, cv));
            float mn = fminf(a, fminf(bv, cv));
            float md = fmaxf(fminf(a, bv), fminf(fmaxf(a, bv), cv));
            float v  = mx + __logf(1.f + __expf(md - mx) + __expf(mn - mx));
            A[cur][s] = v + e_cur;
        }
        __syncthreads();
    }

    if (s == 0) {
        const int f = (len - 1) & 1;
        float l1 = A[f][2 * L - 1];
        float l2 = A[f][2 * L];
        float m = fmaxf(l1, l2);
        float last = m + logf(expf(l1 - m) + expf(l2 - m));
        float nll = (last > 0.5f * NEGV) ? -last : 0.f;
        g_loss[b] = nll / (float)len;
    }
}

__global__ __launch_bounds__(32) void k_reduce(float* __restrict__ out) {
    float v = g_loss[threadIdx.x];
#pragma unroll
    for (int o = 16; o > 0; o >>= 1) v += __shfl_xor_sync(0xffffffffu, v, o);
    if (threadIdx.x == 0) out[0] = v * (1.0f / BB);
}

// ---------------------------------------------------------------------------
extern "C" void kernel_launch(void* const* d_in, const int* in_sizes, int n_in,
                              void* d_out, int out_size) {
    const float* dec  = (const float*)d_in[0];
    const int*   tgt  = (const int*)d_in[1];
    const int*   dlen = (const int*)d_in[2];
    const int*   tlen = (const int*)d_in[3];
    const float* W1   = (const float*)d_in[4];
    const float* b1   = (const float*)d_in[5];
    const float* W2   = (const float*)d_in[6];
    const float* b2   = (const float*)d_in[7];
    float* out = (float*)d_out;

    const int SMEM1 = 197632;  // pad + 2 x 98304 stages (epilogue reuses)
    const int SMEM2 = 115712;  // pad + 2 x 57344 stages
    cudaFuncSetAttribute(k_gemm1, cudaFuncAttributeMaxDynamicSharedMemorySize, SMEM1);
    cudaFuncSetAttribute(k_gemm2, cudaFuncAttributeMaxDynamicSharedMemorySize, SMEM2);

    k_prep_dec<<<dim3(TP / 32, DD / 32, BB), dim3(32, 8)>>>(dec);
    k_prep_w1<<<dim3(DD / 32, DD / 32), dim3(32, 8)>>>(W1);
    k_prep_w2<<<(NTB * DD + 255) / 256, 256>>>(W2);

    k_gemm1<<<dim3(TP / 128, DD / 256, BB), 256, SMEM1>>>(dec, W1, b1);
    k_gemm2<<<dim3(TP / 128, BB), 256, SMEM2>>>(b2);

    k_ctc<<<BB, 448>>>(tgt, dlen, tlen);
    k_reduce<<<1, 32>>>(out);
}

// round 11
// speedup vs baseline: 1.4016x; 1.4016x over previous
#include <cuda_runtime.h>
#include <cuda_bf16.h>
#include <math.h>
#include <stdint.h>

#define BB 32
#define DD 1024
#define TT 1000
#define TP 1024
#define VV 80
#define NTB 96
#define LMAX 200
#define BLANK 79
#define NEGV (-1e30f)

#if defined(__CUDA_ARCH_FEAT_SM103_ALL) || defined(__CUDA_ARCH_FEAT_SM100_ALL)
#define HAS_TCGEN05 1
#else
#define HAS_TCGEN05 0
#endif

// ---------------- scratch ----------------------------------------------------
__device__ __nv_bfloat16 g_xh[(size_t)BB * TP * DD];
__device__ __nv_bfloat16 g_xl[(size_t)BB * TP * DD];
__device__ __nv_bfloat16 g_w1h[(size_t)DD * DD];
__device__ __nv_bfloat16 g_w1l[(size_t)DD * DD];
__device__ __nv_bfloat16 g_w2h[(size_t)NTB * DD];
__device__ __nv_bfloat16 g_w2l[(size_t)NTB * DD];
__device__ __nv_bfloat16 g_hh[(size_t)BB * TP * DD];
__device__ __nv_bfloat16 g_hl[(size_t)BB * TP * DD];
__device__ float         g_lp[(size_t)BB * TT * VV];
__device__ float         g_loss[BB];

// ---------------- PTX helpers ------------------------------------------------
__device__ __forceinline__ uint32_t sm_u32(const void* p) {
    uint32_t a;
    asm("{ .reg .u64 t; cvta.to.shared.u64 t, %1; cvt.u32.u64 %0, t; }"
        : "=r"(a) : "l"(p));
    return a;
}
__device__ __forceinline__ bool elect1() {
    uint32_t p;
    asm volatile("{ .reg .pred p; elect.sync _|p, 0xFFFFFFFF; selp.b32 %0,1,0,p; }"
                 : "=r"(p));
    return p != 0;
}
__device__ __forceinline__ uint32_t swz(uint32_t off) { return off ^ ((off >> 3) & 0x70u); }
__device__ __forceinline__ uint64_t mkdesc(uint32_t addr) {
    const uint64_t base = (2ull << 61) | (1ull << 46) | (64ull << 32) | (1ull << 16);
    return base | (uint64_t)((addr >> 4) & 0x3FFF);
}
__device__ __forceinline__ void cp16(uint32_t dst, const void* src) {
    asm volatile("cp.async.cg.shared.global [%0], [%1], 16;" :: "r"(dst), "l"(src));
}
#define CP_COMMIT() asm volatile("cp.async.commit_group;" ::: "memory")
__device__ __forceinline__ void mbar_wait(uint32_t mbar, uint32_t parity) {
    asm volatile(
        "{\n\t.reg .pred P;\n\t"
        "WL%=:\n\t"
        "mbarrier.try_wait.parity.acquire.cta.shared::cta.b64 P, [%0], %1;\n\t"
        "@!P bra WL%=;\n\t}"
        :: "r"(mbar), "r"(parity) : "memory");
}

#if HAS_TCGEN05
__device__ __forceinline__ void mma_bf16_ss(uint32_t d, uint64_t ad, uint64_t bd,
                                            uint32_t idesc, bool acc) {
    uint32_t en = acc ? 1u : 0u;
    asm volatile(
        "{\n\t.reg .pred p;\n\t"
        "setp.ne.u32 p, %5, 0;\n\t"
        "tcgen05.mma.cta_group::1.kind::f16 [%0], %1, %2, %3, {%4,%4,%4,%4}, p;\n\t}"
        :: "r"(d), "l"(ad), "l"(bd), "r"(idesc), "r"(0u), "r"(en) : "memory");
}
#define LDTM_X32(r, a) asm volatile( \
    "tcgen05.ld.sync.aligned.32x32b.x32.b32 " \
    "{%0,%1,%2,%3,%4,%5,%6,%7,%8,%9,%10,%11,%12,%13,%14,%15," \
    "%16,%17,%18,%19,%20,%21,%22,%23,%24,%25,%26,%27,%28,%29,%30,%31}, [%32];" \
    : "=r"((r)[0]),"=r"((r)[1]),"=r"((r)[2]),"=r"((r)[3]), \
      "=r"((r)[4]),"=r"((r)[5]),"=r"((r)[6]),"=r"((r)[7]), \
      "=r"((r)[8]),"=r"((r)[9]),"=r"((r)[10]),"=r"((r)[11]), \
      "=r"((r)[12]),"=r"((r)[13]),"=r"((r)[14]),"=r"((r)[15]), \
      "=r"((r)[16]),"=r"((r)[17]),"=r"((r)[18]),"=r"((r)[19]), \
      "=r"((r)[20]),"=r"((r)[21]),"=r"((r)[22]),"=r"((r)[23]), \
      "=r"((r)[24]),"=r"((r)[25]),"=r"((r)[26]),"=r"((r)[27]), \
      "=r"((r)[28]),"=r"((r)[29]),"=r"((r)[30]),"=r"((r)[31]) \
    : "r"(a))
#define LDTM_X16(r, a) asm volatile( \
    "tcgen05.ld.sync.aligned.32x32b.x16.b32 " \
    "{%0,%1,%2,%3,%4,%5,%6,%7,%8,%9,%10,%11,%12,%13,%14,%15}, [%16];" \
    : "=r"((r)[0]),"=r"((r)[1]),"=r"((r)[2]),"=r"((r)[3]), \
      "=r"((r)[4]),"=r"((r)[5]),"=r"((r)[6]),"=r"((r)[7]), \
      "=r"((r)[8]),"=r"((r)[9]),"=r"((r)[10]),"=r"((r)[11]), \
      "=r"((r)[12]),"=r"((r)[13]),"=r"((r)[14]),"=r"((r)[15]) \
    : "r"(a))
#define TM_WAIT_LD() asm volatile("tcgen05.wait::ld.sync.aligned;" ::: "memory")
#endif

// ---------------- pre-passes -------------------------------------------------
__global__ __launch_bounds__(256) void k_prep_dec(const float* __restrict__ dec) {
    __shared__ float s[32][33];
    const int b = blockIdx.z, t0 = blockIdx.x * 32, d0 = blockIdx.y * 32;
    const int tx = threadIdx.x, ty = threadIdx.y;
    const float* in = dec + (size_t)b * DD * TT;
#pragma unroll
    for (int i = 0; i < 4; i++) {
        int d = d0 + ty + 8 * i, t = t0 + tx;
        s[ty + 8 * i][tx] = (t < TT) ? in[(size_t)d * TT + t] : 0.f;
    }
    __syncthreads();
#pragma unroll
    for (int i = 0; i < 4; i++) {
        int t = t0 + ty + 8 * i, d = d0 + tx;
        float v = s[tx][ty + 8 * i];
        __nv_bfloat16 hi = __float2bfloat16_rn(v);
        __nv_bfloat16 lo = __float2bfloat16_rn(v - __bfloat162float(hi));
        size_t idx = (size_t)b * TP * DD + (size_t)t * DD + d;
        g_xh[idx] = hi;
        g_xl[idx] = lo;
    }
}
__global__ __launch_bounds__(256) void k_prep_w1(const float* __restrict__ W1) {
    __shared__ float s[32][33];
    const int e0 = blockIdx.x * 32, d0 = blockIdx.y * 32;
    const int tx = threadIdx.x, ty = threadIdx.y;
#pragma unroll
    for (int i = 0; i < 4; i++)
        s[ty + 8 * i][tx] = W1[(size_t)(d0 + ty + 8 * i) * DD + e0 + tx];
    __syncthreads();
#pragma unroll
    for (int i = 0; i < 4; i++) {
        float v = s[tx][ty + 8 * i];
        __nv_bfloat16 hi = __float2bfloat16_rn(v);
        __nv_bfloat16 lo = __float2bfloat16_rn(v - __bfloat162float(hi));
        size_t idx = (size_t)(e0 + ty + 8 * i) * DD + d0 + tx;
        g_w1h[idx] = hi;
        g_w1l[idx] = lo;
    }
}
__global__ __launch_bounds__(256) void k_prep_w2(const float* __restrict__ W2) {
    int idx = blockIdx.x * 256 + threadIdx.x;
    if (idx < NTB * DD) {
        int v = idx / DD, d = idx - v * DD;
        float x = (v < VV) ? W2[(size_t)d * VV + v] : 0.f;
        __nv_bfloat16 hi = __float2bfloat16_rn(x);
        __nv_bfloat16 lo = __float2bfloat16_rn(x - __bfloat162float(hi));
        g_w2h[idx] = hi;
        g_w2l[idx] = lo;
    }
}

// ---------------- GEMM1: N-tile 256, split-bf16, R6-style pipeline -----------
__global__ __launch_bounds__(256) void k_gemm1(const float* __restrict__ dec,
                                               const float* __restrict__ W1,
                                               const float* __restrict__ b1) {
    const int tid = threadIdx.x;
    const int b = blockIdx.z, m0 = blockIdx.x * 128, n0 = blockIdx.y * 256;

#if HAS_TCGEN05
    constexpr int ASZ = 16384;           // 128 rows x 128B
    constexpr int BSZ = 32768;           // 256 rows x 128B
    constexpr int STAGE = 2 * ASZ + 2 * BSZ;  // 98304
    constexpr int NKB = DD / 64;         // 16
    extern __shared__ char dyn_raw[];
    __shared__ uint32_t s_tmem;
    __shared__ __align__(8) uint64_t s_mbar;

    const int wid = tid >> 5, lid = tid & 31;
    const uint32_t raw = sm_u32(dyn_raw);
    const uint32_t sb = (raw + 1023u) & ~1023u;
    char* dynsm = dyn_raw + (sb - raw);

    if (wid == 0) {
        asm volatile("tcgen05.alloc.cta_group::1.sync.aligned.shared::cta.b32 [%0], %1;"
                     :: "r"(sm_u32(&s_tmem)), "r"(256u) : "memory");
        asm volatile("tcgen05.relinquish_alloc_permit.cta_group::1.sync.aligned;");
        if (elect1())
            asm volatile("mbarrier.init.shared.b64 [%0], 1;"
                         :: "r"(sm_u32(&s_mbar)) : "memory");
    }
    __syncthreads();
    const uint32_t tmem = s_tmem;
    const uint32_t mbar = sm_u32(&s_mbar);

    const __nv_bfloat16* Ah = g_xh + (size_t)b * TP * DD + (size_t)m0 * DD;
    const __nv_bfloat16* Al = g_xl + (size_t)b * TP * DD + (size_t)m0 * DD;
    const __nv_bfloat16* Bh = g_w1h + (size_t)n0 * DD;
    const __nv_bfloat16* Bl = g_w1l + (size_t)n0 * DD;

    auto ldstage = [&](int st, int kb) {
        const int k0 = kb * 64;
        const uint32_t su = sb + st * STAGE;
#pragma unroll
        for (int i = 0; i < 24; i++) {
            int c = tid + i * 256;   // 0..6143 (16B chunks)
            uint32_t dst;
            const __nv_bfloat16* src;
            if (c < 1024) {
                int r = c >> 3, ch = c & 7;
                dst = su + swz((uint32_t)(r * 128 + ch * 16));
                src = Ah + (size_t)r * DD + k0 + ch * 8;
            } else if (c < 2048) {
                int cc = c - 1024, r = cc >> 3, ch = cc & 7;
                dst = su + ASZ + swz((uint32_t)(r * 128 + ch * 16));
                src = Al + (size_t)r * DD + k0 + ch * 8;
            } else if (c < 4096) {
                int cc = c - 2048, r = cc >> 3, ch = cc & 7;   // r 0..255
                dst = su + 2 * ASZ + swz((uint32_t)(r * 128 + ch * 16));
                src = Bh + (size_t)r * DD + k0 + ch * 8;
            } else {
                int cc = c - 4096, r = cc >> 3, ch = cc & 7;
                dst = su + 2 * ASZ + BSZ + swz((uint32_t)(r * 128 + ch * 16));
                src = Bl + (size_t)r * DD + k0 + ch * 8;
            }
            cp16(dst, src);
        }
    };

    ldstage(0, 0);
    CP_COMMIT();

    const uint32_t idesc = (1u << 4) | (1u << 7) | (1u << 10) |
                           (16u << 17) | (8u << 24);   // N=128, M=128

    for (int kb = 0; kb < NKB; kb++) {
        const int st = kb & 1;
        if (kb + 1 < NKB) ldstage(st ^ 1, kb + 1);
        CP_COMMIT();
        asm volatile("cp.async.wait_group 1;" ::: "memory");
        __syncthreads();
        if (wid == 0) {
            asm volatile("fence.proxy.async.shared::cta;" ::: "memory");
            if (elect1()) {
                const uint32_t su = sb + st * STAGE;
                uint64_t ah  = mkdesc(su);
                uint64_t al  = mkdesc(su + ASZ);
                uint64_t bh0 = mkdesc(su + 2 * ASZ);
                uint64_t bh1 = mkdesc(su + 2 * ASZ + ASZ);       // rows 128..255
                uint64_t bl0 = mkdesc(su + 2 * ASZ + BSZ);
                uint64_t bl1 = mkdesc(su + 2 * ASZ + BSZ + ASZ);
#pragma unroll
                for (int s4 = 0; s4 < 4; s4++) {
                    uint64_t o = 2 * s4;
                    bool first = (kb == 0 && s4 == 0);
                    mma_bf16_ss(tmem,       ah + o, bh0 + o, idesc, !first);
                    mma_bf16_ss(tmem,       ah + o, bl0 + o, idesc, true);
                    mma_bf16_ss(tmem,       al + o, bh0 + o, idesc, true);
                    mma_bf16_ss(tmem + 128, ah + o, bh1 + o, idesc, !first);
                    mma_bf16_ss(tmem + 128, ah + o, bl1 + o, idesc, true);
                    mma_bf16_ss(tmem + 128, al + o, bh1 + o, idesc, true);
                }
                asm volatile(
                    "tcgen05.commit.cta_group::1.mbarrier::arrive::one.shared::cluster.b64 [%0];"
                    :: "r"(mbar) : "memory");
            }
        }
        mbar_wait(mbar, (uint32_t)(kb & 1));
    }

    asm volatile("tcgen05.fence::after_thread_sync;" ::: "memory");
    __syncthreads();

    // epilogue: TMEM(256 cols) -> smem fp32 -> bias+relu -> split bf16 hi/lo
    float* sh = (float*)dynsm;  // stride 261 floats, 128 rows (133.6KB)
    if (wid < 4) {
        const int row = wid * 32 + lid;
#pragma unroll
        for (int c4 = 0; c4 < 8; c4++) {
            uint32_t r[32];
            LDTM_X32(r, tmem + c4 * 32);
            TM_WAIT_LD();
#pragma unroll
            for (int j = 0; j < 32; j++)
                sh[row * 261 + c4 * 32 + j] = __uint_as_float(r[j]);
        }
        asm volatile("tcgen05.fence::before_thread_sync;" ::: "memory");
    }
    __syncthreads();
#pragma unroll 4
    for (int i = 0; i < 64; i++) {
        int idx = tid + i * 256;               // pair idx over 128x128
        int r = idx >> 7, cp2 = (idx & 127) * 2;
        float v0 = fmaxf(sh[r * 261 + cp2] + b1[n0 + cp2], 0.f);
        float v1 = fmaxf(sh[r * 261 + cp2 + 1] + b1[n0 + cp2 + 1], 0.f);
        __nv_bfloat16 h0 = __float2bfloat16_rn(v0);
        __nv_bfloat16 h1 = __float2bfloat16_rn(v1);
        __nv_bfloat16 l0 = __float2bfloat16_rn(v0 - __bfloat162float(h0));
        __nv_bfloat16 l1 = __float2bfloat16_rn(v1 - __bfloat162float(h1));
        size_t off = ((size_t)b * TP + m0 + r) * DD + n0 + cp2;
        *reinterpret_cast<__nv_bfloat162*>(&g_hh[off]) = __nv_bfloat162(h0, h1);
        *reinterpret_cast<__nv_bfloat162*>(&g_hl[off]) = __nv_bfloat162(l0, l1);
    }
    __syncthreads();
    if (wid == 0)
        asm volatile("tcgen05.dealloc.cta_group::1.sync.aligned.b32 %0, %1;"
                     :: "r"(tmem), "r"(256u));

#else  // SIMT fallback (compile-only on non-103a pass)
    __shared__ float As[16][128];
    __shared__ float Bs[16][128];
    const int tx = tid & 15, ty = tid >> 4;
    const float* A = dec + (size_t)b * DD * TT;
    for (int nh = 0; nh < 2; nh++) {
        const int n0h = n0 + nh * 128;
        float acc[8][8];
#pragma unroll
        for (int i = 0; i < 8; i++)
#pragma unroll
            for (int j = 0; j < 8; j++) acc[i][j] = 0.f;
        for (int k0 = 0; k0 < DD; k0 += 16) {
            __syncthreads();
#pragma unroll
            for (int i = 0; i < 8; i++) {
                int idx = tid + i * 256;
                int kk = idx >> 7, mm = idx & 127;
                int m = m0 + mm;
                As[kk][mm] = (m < TT) ? A[(size_t)(k0 + kk) * TT + m] : 0.f;
                Bs[kk][mm] = W1[(size_t)(k0 + kk) * DD + n0h + mm];
            }
            __syncthreads();
#pragma unroll
            for (int kk = 0; kk < 16; kk++) {
                float a[8], w[8];
#pragma unroll
                for (int i = 0; i < 8; i++) a[i] = As[kk][ty * 8 + i];
#pragma unroll
                for (int j = 0; j < 8; j++) w[j] = Bs[kk][tx * 8 + j];
#pragma unroll
                for (int i = 0; i < 8; i++)
#pragma unroll
                    for (int j = 0; j < 8; j++) acc[i][j] = fmaf(a[i], w[j], acc[i][j]);
            }
        }
#pragma unroll
        for (int i = 0; i < 8; i++) {
            int m = m0 + ty * 8 + i;
#pragma unroll
            for (int j = 0; j < 8; j++) {
                int n = n0h + tx * 8 + j;
                float v = fmaxf(acc[i][j] + b1[n], 0.f);
                __nv_bfloat16 hi = __float2bfloat16_rn(v);
                size_t off = ((size_t)b * TP + m) * DD + n;
                g_hh[off] = hi;
                g_hl[off] = __float2bfloat16_rn(v - __bfloat162float(hi));
            }
        }
        __syncthreads();
    }
#endif
}

// ---------------- GEMM2 + fused softmax, R6-style pipeline -------------------
__global__ __launch_bounds__(256) void k_gemm2(const float* __restrict__ b2) {
    const int tid = threadIdx.x;
    const int b = blockIdx.y, m0 = blockIdx.x * 128;

#if HAS_TCGEN05
    constexpr int ASZ = 16384;
    constexpr int BSZ = NTB * 128;            // 12288
    constexpr int STAGE = 2 * ASZ + 2 * BSZ;  // 57344
    constexpr int NKB = DD / 64;
    extern __shared__ char dyn_raw[];
    __shared__ uint32_t s_tmem;
    __shared__ __align__(8) uint64_t s_mbar;

    const int wid = tid >> 5, lid = tid & 31;
    const uint32_t raw = sm_u32(dyn_raw);
    const uint32_t sb = (raw + 1023u) & ~1023u;
    char* dynsm = dyn_raw + (sb - raw);

    if (wid == 0) {
        asm volatile("tcgen05.alloc.cta_group::1.sync.aligned.shared::cta.b32 [%0], %1;"
                     :: "r"(sm_u32(&s_tmem)), "r"(128u) : "memory");
        asm volatile("tcgen05.relinquish_alloc_permit.cta_group::1.sync.aligned;");
        if (elect1())
            asm volatile("mbarrier.init.shared.b64 [%0], 1;"
                         :: "r"(sm_u32(&s_mbar)) : "memory");
    }
    __syncthreads();
    const uint32_t tmem = s_tmem;
    const uint32_t mbar = sm_u32(&s_mbar);

    const __nv_bfloat16* Ah = g_hh + (size_t)b * TP * DD + (size_t)m0 * DD;
    const __nv_bfloat16* Al = g_hl + (size_t)b * TP * DD + (size_t)m0 * DD;

    auto ldstage = [&](int st, int kb) {
        const int k0 = kb * 64;
        const uint32_t su = sb + st * STAGE;
#pragma unroll
        for (int i = 0; i < 14; i++) {
            int c = tid + i * 256;
            uint32_t dst;
            const __nv_bfloat16* src;
            if (c < 1024) {
                int r = c >> 3, ch = c & 7;
                dst = su + swz((uint32_t)(r * 128 + ch * 16));
                src = Ah + (size_t)r * DD + k0 + ch * 8;
            } else if (c < 2048) {
                int cc = c - 1024, r = cc >> 3, ch = cc & 7;
                dst = su + ASZ + swz((uint32_t)(r * 128 + ch * 16));
                src = Al + (size_t)r * DD + k0 + ch * 8;
            } else if (c < 2816) {
                int cc = c - 2048, r = cc >> 3, ch = cc & 7;
                dst = su + 2 * ASZ + swz((uint32_t)(r * 128 + ch * 16));
                src = g_w2h + (size_t)r * DD + k0 + ch * 8;
            } else {
                int cc = c - 2816, r = cc >> 3, ch = cc & 7;
                dst = su + 2 * ASZ + BSZ + swz((uint32_t)(r * 128 + ch * 16));
                src = g_w2l + (size_t)r * DD + k0 + ch * 8;
            }
            cp16(dst, src);
        }
    };

    ldstage(0, 0);
    CP_COMMIT();

    const uint32_t idesc = (1u << 4) | (1u << 7) | (1u << 10) |
                           ((uint32_t)(NTB / 8) << 17) | (8u << 24);

    for (int kb = 0; kb < NKB; kb++) {
        const int st = kb & 1;
        if (kb + 1 < NKB) ldstage(st ^ 1, kb + 1);
        CP_COMMIT();
        asm volatile("cp.async.wait_group 1;" ::: "memory");
        __syncthreads();
        if (wid == 0) {
            asm volatile("fence.proxy.async.shared::cta;" ::: "memory");
            if (elect1()) {
                const uint32_t su = sb + st * STAGE;
                uint64_t ah = mkdesc(su);
                uint64_t al = mkdesc(su + ASZ);
                uint64_t bh = mkdesc(su + 2 * ASZ);
                uint64_t bl = mkdesc(su + 2 * ASZ + BSZ);
#pragma unroll
                for (int s4 = 0; s4 < 4; s4++) {
                    uint64_t o = 2 * s4;
                    mma_bf16_ss(tmem, ah + o, bh + o, idesc, !(kb == 0 && s4 == 0));
                    mma_bf16_ss(tmem, ah + o, bl + o, idesc, true);
                    mma_bf16_ss(tmem, al + o, bh + o, idesc, true);
                }
                asm volatile(
                    "tcgen05.commit.cta_group::1.mbarrier::arrive::one.shared::cluster.b64 [%0];"
                    :: "r"(mbar) : "memory");
            }
        }
        mbar_wait(mbar, (uint32_t)(kb & 1));
    }

    asm volatile("tcgen05.fence::after_thread_sync;" ::: "memory");
    __syncthreads();

    float* sh = (float*)dynsm;  // [128][81]
    if (wid < 4) {
        float v[VV];
        {
            uint32_t r[32];
            LDTM_X32(r, tmem);
            TM_WAIT_LD();
#pragma unroll
            for (int j = 0; j < 32; j++) v[j] = __uint_as_float(r[j]);
        }
        {
            uint32_t r[32];
            LDTM_X32(r, tmem + 32);
            TM_WAIT_LD();
#pragma unroll
            for (int j = 0; j < 32; j++) v[32 + j] = __uint_as_float(r[j]);
        }
        {
            uint32_t r[16];
            LDTM_X16(r, tmem + 64);
            TM_WAIT_LD();
#pragma unroll
            for (int j = 0; j < 16; j++) v[64 + j] = __uint_as_float(r[j]);
        }
        asm volatile("tcgen05.fence::before_thread_sync;" ::: "memory");
        float mx = -1e30f;
#pragma unroll
        for (int j = 0; j < VV; j++) { v[j] += b2[j]; mx = fmaxf(mx, v[j]); }
        float sum = 0.f;
#pragma unroll
        for (int j = 0; j < VV; j++) sum += expf(v[j] - mx);
        const float lse = mx + logf(sum);
        const int row = wid * 32 + lid;
#pragma unroll
        for (int j = 0; j < VV; j++) sh[row * 81 + j] = v[j] - lse;
    }
    __syncthreads();
#pragma unroll 4
    for (int i = 0; i < 40; i++) {
        int idx = tid + i * 256;
        int rr = idx / 80, cc = idx - rr * 80;
        int t = m0 + rr;
        if (t < TT) g_lp[((size_t)b * TT + t) * VV + cc] = sh[rr * 81 + cc];
    }
    __syncthreads();
    if (wid == 0)
        asm volatile("tcgen05.dealloc.cta_group::1.sync.aligned.b32 %0, %1;"
                     :: "r"(tmem), "r"(128u));

#else  // SIMT fallback (compile-only)
    const int r = m0 + (tid & 127);
    if (tid < 128) {
        float v[VV];
        for (int j = 0; j < VV; j++) v[j] = b2[j];
        const __nv_bfloat16* hh = g_hh + ((size_t)b * TP + r) * DD;
        const __nv_bfloat16* hl = g_hl + ((size_t)b * TP + r) * DD;
        for (int k = 0; k < DD; k++) {
            float hv = __bfloat162float(hh[k]) + __bfloat162float(hl[k]);
            for (int j = 0; j < VV; j++)
                v[j] = fmaf(hv, __bfloat162float(g_w2h[(size_t)j * DD + k]) +
                                 __bfloat162float(g_w2l[(size_t)j * DD + k]), v[j]);
        }
        float mx = -1e30f;
        for (int j = 0; j < VV; j++) mx = fmaxf(mx, v[j]);
        float sum = 0.f;
        for (int j = 0; j < VV; j++) sum += expf(v[j] - mx);
        float lse = mx + logf(sum);
        if (r < TT)
            for (int j = 0; j < VV; j++)
                g_lp[((size_t)b * TT + r) * VV + j] = v[j] - lse;
    }
#endif
}

// ---------------- CTC DP: median-trick lse3 + early-exit + reg prefetch ------
__global__ __launch_bounds__(448) void k_ctc(const int* __restrict__ tgt,
                                             const int* __restrict__ dlen,
                                             const int* __restrict__ tlen) {
    const int b = blockIdx.x;
    const int L = tlen[b];
    const int S = 2 * L + 1;
    const int len = dlen[b];
    const int s = threadIdx.x;

    if (s >= ((S + 31) & ~31)) return;  // retire unused warps entirely

    __shared__ float A[2][2 * LMAX + 1];
    __shared__ int ext[2 * LMAX + 1];

    const float* lpb = g_lp + (size_t)b * TT * VV;

    int lbl = BLANK;
    if (s < S) {
        lbl = (s & 1) ? tgt[b * LMAX + (s >> 1)] : BLANK;
        ext[s] = lbl;
    }
    __syncthreads();
    bool sk = false;
    if (s < S) {
        sk = ((s & 1) && s >= 3 && lbl != ext[s - 2]);
        float a0 = NEGV;
        if (s == 0)      a0 = lpb[BLANK];
        else if (s == 1) a0 = lpb[lbl];
        A[0][s] = a0;
    }

    float eA = 0.f, eB = 0.f;
    if (s < S) {
        int t1 = (1 < len) ? 1 : len - 1;
        int t2 = (2 < len) ? 2 : len - 1;
        eA = lpb[(size_t)t1 * VV + lbl];
        eB = lpb[(size_t)t2 * VV + lbl];
    }
    __syncthreads();

    for (int t = 1; t < len; t++) {
        const int cur = t & 1, prev = cur ^ 1;
        float e_cur = eA;
        eA = eB;
        if (s < S) {
            int tn = (t + 2 < len) ? t + 2 : len - 1;
            eB = lpb[(size_t)tn * VV + lbl];
            float a  = A[prev][s];
            float bv = (s >= 1) ? A[prev][s - 1] : NEGV;
            float cv = sk ? A[prev][s - 2] : NEGV;
            float mx = fmaxf(a, fmaxf(bv, cv));
            float mn = fminf(a, fminf(bv, cv));
            float md = fmaxf(fminf(a, bv), fminf(fmaxf(a, bv), cv));
            float v  = mx + __logf(1.f + __expf(md - mx) + __expf(mn - mx));
            A[cur][s] = v + e_cur;
        }
        __syncthreads();
    }

    if (s == 0) {
        const int f = (len - 1) & 1;
        float l1 = A[f][2 * L - 1];
        float l2 = A[f][2 * L];
        float m = fmaxf(l1, l2);
        float last = m + logf(expf(l1 - m) + expf(l2 - m));
        float nll = (last > 0.5f * NEGV) ? -last : 0.f;
        g_loss[b] = nll / (float)len;
    }
}

__global__ __launch_bounds__(32) void k_reduce(float* __restrict__ out) {
    float v = g_loss[threadIdx.x];
#pragma unroll
    for (int o = 16; o > 0; o >>= 1) v += __shfl_xor_sync(0xffffffffu, v, o);
    if (threadIdx.x == 0) out[0] = v * (1.0f / BB);
}

// ---------------------------------------------------------------------------
extern "C" void kernel_launch(void* const* d_in, const int* in_sizes, int n_in,
                              void* d_out, int out_size) {
    const float* dec  = (const float*)d_in[0];
    const int*   tgt  = (const int*)d_in[1];
    const int*   dlen = (const int*)d_in[2];
    const int*   tlen = (const int*)d_in[3];
    const float* W1   = (const float*)d_in[4];
    const float* b1   = (const float*)d_in[5];
    const float* W2   = (const float*)d_in[6];
    const float* b2   = (const float*)d_in[7];
    float* out = (float*)d_out;

    const int SMEM1 = 197632;  // pad + 2 x 98304 stages (epilogue reuses)
    const int SMEM2 = 115712;  // pad + 2 x 57344 stages
    cudaFuncSetAttribute(k_gemm1, cudaFuncAttributeMaxDynamicSharedMemorySize, SMEM1);
    cudaFuncSetAttribute(k_gemm2, cudaFuncAttributeMaxDynamicSharedMemorySize, SMEM2);

    k_prep_dec<<<dim3(TP / 32, DD / 32, BB), dim3(32, 8)>>>(dec);
    k_prep_w1<<<dim3(DD / 32, DD / 32), dim3(32, 8)>>>(W1);
    k_prep_w2<<<(NTB * DD + 255) / 256, 256>>>(W2);

    k_gemm1<<<dim3(TP / 128, DD / 256, BB), 256, SMEM1>>>(dec, W1, b1);
    k_gemm2<<<dim3(TP / 128, BB), 256, SMEM2>>>(b2);

    k_ctc<<<BB, 448>>>(tgt, dlen, tlen);
    k_reduce<<<1, 32>>>(out);
}

// round 12
// speedup vs baseline: 1.6468x; 1.1749x over previous
#include <cuda_runtime.h>
#include <cuda_bf16.h>
#include <math.h>
#include <stdint.h>

#define BB 32
#define DD 1024
#define TT 1000
#define TP 1024
#define VV 80
#define NTB 96
#define LMAX 200
#define BLANK 79
#define NEGV (-1e30f)

#if defined(__CUDA_ARCH_FEAT_SM103_ALL) || defined(__CUDA_ARCH_FEAT_SM100_ALL)
#define HAS_TCGEN05 1
#else
#define HAS_TCGEN05 0
#endif

// ---------------- scratch ----------------------------------------------------
__device__ __nv_bfloat16 g_xh[(size_t)BB * TP * DD];   // dec bf16 (hi only)
__device__ __nv_bfloat16 g_w1h[(size_t)DD * DD];       // W1 hi, [e][d]
__device__ __nv_bfloat16 g_w1l[(size_t)DD * DD];       // W1 lo (systematic -> keep)
__device__ __nv_bfloat16 g_w2h[(size_t)NTB * DD];      // W2 hi
__device__ __nv_bfloat16 g_w2l[(size_t)NTB * DD];      // W2 lo
__device__ __nv_bfloat16 g_hb[(size_t)BB * TP * DD];   // h bf16 (hi only)
__device__ float         g_lp[(size_t)BB * TT * VV];
__device__ float         g_loss[BB];

// ---------------- PTX helpers ------------------------------------------------
__device__ __forceinline__ uint32_t sm_u32(const void* p) {
    uint32_t a;
    asm("{ .reg .u64 t; cvta.to.shared.u64 t, %1; cvt.u32.u64 %0, t; }"
        : "=r"(a) : "l"(p));
    return a;
}
__device__ __forceinline__ bool elect1() {
    uint32_t p;
    asm volatile("{ .reg .pred p; elect.sync _|p, 0xFFFFFFFF; selp.b32 %0,1,0,p; }"
                 : "=r"(p));
    return p != 0;
}
__device__ __forceinline__ uint32_t swz(uint32_t off) { return off ^ ((off >> 3) & 0x70u); }
__device__ __forceinline__ uint64_t mkdesc(uint32_t addr) {
    const uint64_t base = (2ull << 61) | (1ull << 46) | (64ull << 32) | (1ull << 16);
    return base | (uint64_t)((addr >> 4) & 0x3FFF);
}
__device__ __forceinline__ void cp16(uint32_t dst, const void* src) {
    asm volatile("cp.async.cg.shared.global [%0], [%1], 16;" :: "r"(dst), "l"(src));
}
#define CP_COMMIT() asm volatile("cp.async.commit_group;" ::: "memory")
__device__ __forceinline__ void mbar_wait(uint32_t mbar, uint32_t parity) {
    asm volatile(
        "{\n\t.reg .pred P;\n\t"
        "WL%=:\n\t"
        "mbarrier.try_wait.parity.acquire.cta.shared::cta.b64 P, [%0], %1;\n\t"
        "@!P bra WL%=;\n\t}"
        :: "r"(mbar), "r"(parity) : "memory");
}

#if HAS_TCGEN05
__device__ __forceinline__ void mma_bf16_ss(uint32_t d, uint64_t ad, uint64_t bd,
                                            uint32_t idesc, bool acc) {
    uint32_t en = acc ? 1u : 0u;
    asm volatile(
        "{\n\t.reg .pred p;\n\t"
        "setp.ne.u32 p, %5, 0;\n\t"
        "tcgen05.mma.cta_group::1.kind::f16 [%0], %1, %2, %3, {%4,%4,%4,%4}, p;\n\t}"
        :: "r"(d), "l"(ad), "l"(bd), "r"(idesc), "r"(0u), "r"(en) : "memory");
}
#define LDTM_X32(r, a) asm volatile( \
    "tcgen05.ld.sync.aligned.32x32b.x32.b32 " \
    "{%0,%1,%2,%3,%4,%5,%6,%7,%8,%9,%10,%11,%12,%13,%14,%15," \
    "%16,%17,%18,%19,%20,%21,%22,%23,%24,%25,%26,%27,%28,%29,%30,%31}, [%32];" \
    : "=r"((r)[0]),"=r"((r)[1]),"=r"((r)[2]),"=r"((r)[3]), \
      "=r"((r)[4]),"=r"((r)[5]),"=r"((r)[6]),"=r"((r)[7]), \
      "=r"((r)[8]),"=r"((r)[9]),"=r"((r)[10]),"=r"((r)[11]), \
      "=r"((r)[12]),"=r"((r)[13]),"=r"((r)[14]),"=r"((r)[15]), \
      "=r"((r)[16]),"=r"((r)[17]),"=r"((r)[18]),"=r"((r)[19]), \
      "=r"((r)[20]),"=r"((r)[21]),"=r"((r)[22]),"=r"((r)[23]), \
      "=r"((r)[24]),"=r"((r)[25]),"=r"((r)[26]),"=r"((r)[27]), \
      "=r"((r)[28]),"=r"((r)[29]),"=r"((r)[30]),"=r"((r)[31]) \
    : "r"(a))
#define LDTM_X16(r, a) asm volatile( \
    "tcgen05.ld.sync.aligned.32x32b.x16.b32 " \
    "{%0,%1,%2,%3,%4,%5,%6,%7,%8,%9,%10,%11,%12,%13,%14,%15}, [%16];" \
    : "=r"((r)[0]),"=r"((r)[1]),"=r"((r)[2]),"=r"((r)[3]), \
      "=r"((r)[4]),"=r"((r)[5]),"=r"((r)[6]),"=r"((r)[7]), \
      "=r"((r)[8]),"=r"((r)[9]),"=r"((r)[10]),"=r"((r)[11]), \
      "=r"((r)[12]),"=r"((r)[13]),"=r"((r)[14]),"=r"((r)[15]) \
    : "r"(a))
#define TM_WAIT_LD() asm volatile("tcgen05.wait::ld.sync.aligned;" ::: "memory")
#endif

// ---------------- pre-passes -------------------------------------------------
__global__ __launch_bounds__(256) void k_prep_dec(const float* __restrict__ dec) {
    __shared__ float s[32][33];
    const int b = blockIdx.z, t0 = blockIdx.x * 32, d0 = blockIdx.y * 32;
    const int tx = threadIdx.x, ty = threadIdx.y;
    const float* in = dec + (size_t)b * DD * TT;
#pragma unroll
    for (int i = 0; i < 4; i++) {
        int d = d0 + ty + 8 * i, t = t0 + tx;
        s[ty + 8 * i][tx] = (t < TT) ? in[(size_t)d * TT + t] : 0.f;
    }
    __syncthreads();
#pragma unroll
    for (int i = 0; i < 4; i++) {
        int t = t0 + ty + 8 * i, d = d0 + tx;
        g_xh[(size_t)b * TP * DD + (size_t)t * DD + d] =
            __float2bfloat16_rn(s[tx][ty + 8 * i]);
    }
}
__global__ __launch_bounds__(256) void k_prep_w1(const float* __restrict__ W1) {
    __shared__ float s[32][33];
    const int e0 = blockIdx.x * 32, d0 = blockIdx.y * 32;
    const int tx = threadIdx.x, ty = threadIdx.y;
#pragma unroll
    for (int i = 0; i < 4; i++)
        s[ty + 8 * i][tx] = W1[(size_t)(d0 + ty + 8 * i) * DD + e0 + tx];
    __syncthreads();
#pragma unroll
    for (int i = 0; i < 4; i++) {
        float v = s[tx][ty + 8 * i];
        __nv_bfloat16 hi = __float2bfloat16_rn(v);
        __nv_bfloat16 lo = __float2bfloat16_rn(v - __bfloat162float(hi));
        size_t idx = (size_t)(e0 + ty + 8 * i) * DD + d0 + tx;
        g_w1h[idx] = hi;
        g_w1l[idx] = lo;
    }
}
__global__ __launch_bounds__(256) void k_prep_w2(const float* __restrict__ W2) {
    int idx = blockIdx.x * 256 + threadIdx.x;
    if (idx < NTB * DD) {
        int v = idx / DD, d = idx - v * DD;
        float x = (v < VV) ? W2[(size_t)d * VV + v] : 0.f;
        __nv_bfloat16 hi = __float2bfloat16_rn(x);
        __nv_bfloat16 lo = __float2bfloat16_rn(x - __bfloat162float(hi));
        g_w2h[idx] = hi;
        g_w2l[idx] = lo;
    }
}

// ---------------- GEMM1: N-tile 256, A-hi only + W split, R6 pipeline --------
__global__ __launch_bounds__(256) void k_gemm1(const float* __restrict__ dec,
                                               const float* __restrict__ W1,
                                               const float* __restrict__ b1) {
    const int tid = threadIdx.x;
    const int b = blockIdx.z, m0 = blockIdx.x * 128, n0 = blockIdx.y * 256;

#if HAS_TCGEN05
    constexpr int ASZ = 16384;                // Ah: 128 rows x 128B
    constexpr int BSZ = 32768;                // Bh/Bl: 256 rows x 128B
    constexpr int STAGE = ASZ + 2 * BSZ;      // 81920
    constexpr int NKB = DD / 64;              // 16
    extern __shared__ char dyn_raw[];
    __shared__ uint32_t s_tmem;
    __shared__ __align__(8) uint64_t s_mbar;

    const int wid = tid >> 5, lid = tid & 31;
    const uint32_t raw = sm_u32(dyn_raw);
    const uint32_t sb = (raw + 1023u) & ~1023u;
    char* dynsm = dyn_raw + (sb - raw);

    if (wid == 0) {
        asm volatile("tcgen05.alloc.cta_group::1.sync.aligned.shared::cta.b32 [%0], %1;"
                     :: "r"(sm_u32(&s_tmem)), "r"(256u) : "memory");
        asm volatile("tcgen05.relinquish_alloc_permit.cta_group::1.sync.aligned;");
        if (elect1())
            asm volatile("mbarrier.init.shared.b64 [%0], 1;"
                         :: "r"(sm_u32(&s_mbar)) : "memory");
    }
    __syncthreads();
    const uint32_t tmem = s_tmem;
    const uint32_t mbar = sm_u32(&s_mbar);

    const __nv_bfloat16* Ah = g_xh + (size_t)b * TP * DD + (size_t)m0 * DD;
    const __nv_bfloat16* Bh = g_w1h + (size_t)n0 * DD;
    const __nv_bfloat16* Bl = g_w1l + (size_t)n0 * DD;

    auto ldstage = [&](int st, int kb) {
        const int k0 = kb * 64;
        const uint32_t su = sb + st * STAGE;
#pragma unroll
        for (int i = 0; i < 20; i++) {
            int c = tid + i * 256;   // 0..5119 (16B chunks)
            uint32_t dst;
            const __nv_bfloat16* src;
            if (c < 1024) {
                int r = c >> 3, ch = c & 7;
                dst = su + swz((uint32_t)(r * 128 + ch * 16));
                src = Ah + (size_t)r * DD + k0 + ch * 8;
            } else if (c < 3072) {
                int cc = c - 1024, r = cc >> 3, ch = cc & 7;   // r 0..255
                dst = su + ASZ + swz((uint32_t)(r * 128 + ch * 16));
                src = Bh + (size_t)r * DD + k0 + ch * 8;
            } else {
                int cc = c - 3072, r = cc >> 3, ch = cc & 7;
                dst = su + ASZ + BSZ + swz((uint32_t)(r * 128 + ch * 16));
                src = Bl + (size_t)r * DD + k0 + ch * 8;
            }
            cp16(dst, src);
        }
    };

    ldstage(0, 0);
    CP_COMMIT();

    const uint32_t idesc = (1u << 4) | (1u << 7) | (1u << 10) |
                           (16u << 17) | (8u << 24);   // N=128, M=128

    for (int kb = 0; kb < NKB; kb++) {
        const int st = kb & 1;
        if (kb + 1 < NKB) ldstage(st ^ 1, kb + 1);
        CP_COMMIT();
        asm volatile("cp.async.wait_group 1;" ::: "memory");
        __syncthreads();
        if (wid == 0) {
            asm volatile("fence.proxy.async.shared::cta;" ::: "memory");
            if (elect1()) {
                const uint32_t su = sb + st * STAGE;
                uint64_t ah  = mkdesc(su);
                uint64_t bh0 = mkdesc(su + ASZ);
                uint64_t bh1 = mkdesc(su + ASZ + 16384);        // rows 128..255
                uint64_t bl0 = mkdesc(su + ASZ + BSZ);
                uint64_t bl1 = mkdesc(su + ASZ + BSZ + 16384);
#pragma unroll
                for (int s4 = 0; s4 < 4; s4++) {
                    uint64_t o = 2 * s4;
                    bool first = (kb == 0 && s4 == 0);
                    mma_bf16_ss(tmem,       ah + o, bh0 + o, idesc, !first);
                    mma_bf16_ss(tmem,       ah + o, bl0 + o, idesc, true);
                    mma_bf16_ss(tmem + 128, ah + o, bh1 + o, idesc, !first);
                    mma_bf16_ss(tmem + 128, ah + o, bl1 + o, idesc, true);
                }
                asm volatile(
                    "tcgen05.commit.cta_group::1.mbarrier::arrive::one.shared::cluster.b64 [%0];"
                    :: "r"(mbar) : "memory");
            }
        }
        mbar_wait(mbar, (uint32_t)(kb & 1));
    }

    asm volatile("tcgen05.fence::after_thread_sync;" ::: "memory");
    __syncthreads();

    // epilogue: TMEM(256 cols) -> smem fp32 -> bias+relu -> bf16
    float* sh = (float*)dynsm;  // stride 261 floats, 128 rows (133.6KB)
    if (wid < 4) {
        const int row = wid * 32 + lid;
#pragma unroll
        for (int c4 = 0; c4 < 8; c4++) {
            uint32_t r[32];
            LDTM_X32(r, tmem + c4 * 32);
            TM_WAIT_LD();
#pragma unroll
            for (int j = 0; j < 32; j++)
                sh[row * 261 + c4 * 32 + j] = __uint_as_float(r[j]);
        }
        asm volatile("tcgen05.fence::before_thread_sync;" ::: "memory");
    }
    __syncthreads();
#pragma unroll 4
    for (int i = 0; i < 64; i++) {
        int idx = tid + i * 256;               // pair idx over 128x128
        int r = idx >> 7, cp2 = (idx & 127) * 2;
        float v0 = fmaxf(sh[r * 261 + cp2] + b1[n0 + cp2], 0.f);
        float v1 = fmaxf(sh[r * 261 + cp2 + 1] + b1[n0 + cp2 + 1], 0.f);
        *reinterpret_cast<__nv_bfloat162*>(
            &g_hb[((size_t)b * TP + m0 + r) * DD + n0 + cp2]) =
            __floats2bfloat162_rn(v0, v1);
    }
    __syncthreads();
    if (wid == 0)
        asm volatile("tcgen05.dealloc.cta_group::1.sync.aligned.b32 %0, %1;"
                     :: "r"(tmem), "r"(256u));

#else  // SIMT fallback (compile-only on non-103a pass)
    __shared__ float As[16][128];
    __shared__ float Bs[16][128];
    const int tx = tid & 15, ty = tid >> 4;
    const float* A = dec + (size_t)b * DD * TT;
    for (int nh = 0; nh < 2; nh++) {
        const int n0h = n0 + nh * 128;
        float acc[8][8];
#pragma unroll
        for (int i = 0; i < 8; i++)
#pragma unroll
            for (int j = 0; j < 8; j++) acc[i][j] = 0.f;
        for (int k0 = 0; k0 < DD; k0 += 16) {
            __syncthreads();
#pragma unroll
            for (int i = 0; i < 8; i++) {
                int idx = tid + i * 256;
                int kk = idx >> 7, mm = idx & 127;
                int m = m0 + mm;
                As[kk][mm] = (m < TT) ? A[(size_t)(k0 + kk) * TT + m] : 0.f;
                Bs[kk][mm] = W1[(size_t)(k0 + kk) * DD + n0h + mm];
            }
            __syncthreads();
#pragma unroll
            for (int kk = 0; kk < 16; kk++) {
                float a[8], w[8];
#pragma unroll
                for (int i = 0; i < 8; i++) a[i] = As[kk][ty * 8 + i];
#pragma unroll
                for (int j = 0; j < 8; j++) w[j] = Bs[kk][tx * 8 + j];
#pragma unroll
                for (int i = 0; i < 8; i++)
#pragma unroll
                    for (int j = 0; j < 8; j++) acc[i][j] = fmaf(a[i], w[j], acc[i][j]);
            }
        }
#pragma unroll
        for (int i = 0; i < 8; i++) {
            int m = m0 + ty * 8 + i;
#pragma unroll
            for (int j = 0; j < 8; j++) {
                int n = n0h + tx * 8 + j;
                g_hb[((size_t)b * TP + m) * DD + n] =
                    __float2bfloat16_rn(fmaxf(acc[i][j] + b1[n], 0.f));
            }
        }
        __syncthreads();
    }
#endif
}

// ---------------- GEMM2 + fused softmax, A-hi only + W split -----------------
__global__ __launch_bounds__(256) void k_gemm2(const float* __restrict__ b2) {
    const int tid = threadIdx.x;
    const int b = blockIdx.y, m0 = blockIdx.x * 128;

#if HAS_TCGEN05
    constexpr int ASZ = 16384;
    constexpr int BSZ = NTB * 128;            // 12288
    constexpr int STAGE = ASZ + 2 * BSZ;      // 40960
    constexpr int NKB = DD / 64;
    extern __shared__ char dyn_raw[];
    __shared__ uint32_t s_tmem;
    __shared__ __align__(8) uint64_t s_mbar;

    const int wid = tid >> 5, lid = tid & 31;
    const uint32_t raw = sm_u32(dyn_raw);
    const uint32_t sb = (raw + 1023u) & ~1023u;
    char* dynsm = dyn_raw + (sb - raw);

    if (wid == 0) {
        asm volatile("tcgen05.alloc.cta_group::1.sync.aligned.shared::cta.b32 [%0], %1;"
                     :: "r"(sm_u32(&s_tmem)), "r"(128u) : "memory");
        asm volatile("tcgen05.relinquish_alloc_permit.cta_group::1.sync.aligned;");
        if (elect1())
            asm volatile("mbarrier.init.shared.b64 [%0], 1;"
                         :: "r"(sm_u32(&s_mbar)) : "memory");
    }
    __syncthreads();
    const uint32_t tmem = s_tmem;
    const uint32_t mbar = sm_u32(&s_mbar);

    const __nv_bfloat16* Ah = g_hb + (size_t)b * TP * DD + (size_t)m0 * DD;

    auto ldstage = [&](int st, int kb) {
        const int k0 = kb * 64;
        const uint32_t su = sb + st * STAGE;
#pragma unroll
        for (int i = 0; i < 10; i++) {
            int c = tid + i * 256;   // 0..2559
            uint32_t dst;
            const __nv_bfloat16* src;
            if (c < 1024) {
                int r = c >> 3, ch = c & 7;
                dst = su + swz((uint32_t)(r * 128 + ch * 16));
                src = Ah + (size_t)r * DD + k0 + ch * 8;
            } else if (c < 1792) {
                int cc = c - 1024, r = cc >> 3, ch = cc & 7;   // r 0..95
                dst = su + ASZ + swz((uint32_t)(r * 128 + ch * 16));
                src = g_w2h + (size_t)r * DD + k0 + ch * 8;
            } else {
                int cc = c - 1792, r = cc >> 3, ch = cc & 7;
                dst = su + ASZ + BSZ + swz((uint32_t)(r * 128 + ch * 16));
                src = g_w2l + (size_t)r * DD + k0 + ch * 8;
            }
            cp16(dst, src);
        }
    };

    ldstage(0, 0);
    CP_COMMIT();

    const uint32_t idesc = (1u << 4) | (1u << 7) | (1u << 10) |
                           ((uint32_t)(NTB / 8) << 17) | (8u << 24);

    for (int kb = 0; kb < NKB; kb++) {
        const int st = kb & 1;
        if (kb + 1 < NKB) ldstage(st ^ 1, kb + 1);
        CP_COMMIT();
        asm volatile("cp.async.wait_group 1;" ::: "memory");
        __syncthreads();
        if (wid == 0) {
            asm volatile("fence.proxy.async.shared::cta;" ::: "memory");
            if (elect1()) {
                const uint32_t su = sb + st * STAGE;
                uint64_t ah = mkdesc(su);
                uint64_t bh = mkdesc(su + ASZ);
                uint64_t bl = mkdesc(su + ASZ + BSZ);
#pragma unroll
                for (int s4 = 0; s4 < 4; s4++) {
                    uint64_t o = 2 * s4;
                    mma_bf16_ss(tmem, ah + o, bh + o, idesc, !(kb == 0 && s4 == 0));
                    mma_bf16_ss(tmem, ah + o, bl + o, idesc, true);
                }
                asm volatile(
                    "tcgen05.commit.cta_group::1.mbarrier::arrive::one.shared::cluster.b64 [%0];"
                    :: "r"(mbar) : "memory");
            }
        }
        mbar_wait(mbar, (uint32_t)(kb & 1));
    }

    asm volatile("tcgen05.fence::after_thread_sync;" ::: "memory");
    __syncthreads();

    float* sh = (float*)dynsm;  // [128][81]
    if (wid < 4) {
        float v[VV];
        {
            uint32_t r[32];
            LDTM_X32(r, tmem);
            TM_WAIT_LD();
#pragma unroll
            for (int j = 0; j < 32; j++) v[j] = __uint_as_float(r[j]);
        }
        {
            uint32_t r[32];
            LDTM_X32(r, tmem + 32);
            TM_WAIT_LD();
#pragma unroll
            for (int j = 0; j < 32; j++) v[32 + j] = __uint_as_float(r[j]);
        }
        {
            uint32_t r[16];
            LDTM_X16(r, tmem + 64);
            TM_WAIT_LD();
#pragma unroll
            for (int j = 0; j < 16; j++) v[64 + j] = __uint_as_float(r[j]);
        }
        asm volatile("tcgen05.fence::before_thread_sync;" ::: "memory");
        float mx = -1e30f;
#pragma unroll
        for (int j = 0; j < VV; j++) { v[j] += b2[j]; mx = fmaxf(mx, v[j]); }
        float sum = 0.f;
#pragma unroll
        for (int j = 0; j < VV; j++) sum += expf(v[j] - mx);
        const float lse = mx + logf(sum);
        const int row = wid * 32 + lid;
#pragma unroll
        for (int j = 0; j < VV; j++) sh[row * 81 + j] = v[j] - lse;
    }
    __syncthreads();
#pragma unroll 4
    for (int i = 0; i < 40; i++) {
        int idx = tid + i * 256;
        int rr = idx / 80, cc = idx - rr * 80;
        int t = m0 + rr;
        if (t < TT) g_lp[((size_t)b * TT + t) * VV + cc] = sh[rr * 81 + cc];
    }
    __syncthreads();
    if (wid == 0)
        asm volatile("tcgen05.dealloc.cta_group::1.sync.aligned.b32 %0, %1;"
                     :: "r"(tmem), "r"(128u));

#else  // SIMT fallback (compile-only)
    const int r = m0 + (tid & 127);
    if (tid < 128) {
        float v[VV];
        for (int j = 0; j < VV; j++) v[j] = b2[j];
        const __nv_bfloat16* hh = g_hb + ((size_t)b * TP + r) * DD;
        for (int k = 0; k < DD; k++) {
            float hv = __bfloat162float(hh[k]);
            for (int j = 0; j < VV; j++)
                v[j] = fmaf(hv, __bfloat162float(g_w2h[(size_t)j * DD + k]) +
                                 __bfloat162float(g_w2l[(size_t)j * DD + k]), v[j]);
        }
        float mx = -1e30f;
        for (int j = 0; j < VV; j++) mx = fmaxf(mx, v[j]);
        float sum = 0.f;
        for (int j = 0; j < VV; j++) sum += expf(v[j] - mx);
        float lse = mx + logf(sum);
        if (r < TT)
            for (int j = 0; j < VV; j++)
                g_lp[((size_t)b * TT + r) * VV + j] = v[j] - lse;
    }
#endif
}

// ---------------- CTC DP: median-trick lse3 + early-exit + reg prefetch ------
__global__ __launch_bounds__(448) void k_ctc(const int* __restrict__ tgt,
                                             const int* __restrict__ dlen,
                                             const int* __restrict__ tlen) {
    const int b = blockIdx.x;
    const int L = tlen[b];
    const int S = 2 * L + 1;
    const int len = dlen[b];
    const int s = threadIdx.x;

    if (s >= ((S + 31) & ~31)) return;  // retire unused warps entirely

    __shared__ float A[2][2 * LMAX + 1];
    __shared__ int ext[2 * LMAX + 1];

    const float* lpb = g_lp + (size_t)b * TT * VV;

    int lbl = BLANK;
    if (s < S) {
        lbl = (s & 1) ? tgt[b * LMAX + (s >> 1)] : BLANK;
        ext[s] = lbl;
    }
    __syncthreads();
    bool sk = false;
    if (s < S) {
        sk = ((s & 1) && s >= 3 && lbl != ext[s - 2]);
        float a0 = NEGV;
        if (s == 0)      a0 = lpb[BLANK];
        else if (s == 1) a0 = lpb[lbl];
        A[0][s] = a0;
    }

    float eA = 0.f, eB = 0.f;
    if (s < S) {
        int t1 = (1 < len) ? 1 : len - 1;
        int t2 = (2 < len) ? 2 : len - 1;
        eA = lpb[(size_t)t1 * VV + lbl];
        eB = lpb[(size_t)t2 * VV + lbl];
    }
    __syncthreads();

    for (int t = 1; t < len; t++) {
        const int cur = t & 1, prev = cur ^ 1;
        float e_cur = eA;
        eA = eB;
        if (s < S) {
            int tn = (t + 2 < len) ? t + 2 : len - 1;
            eB = lpb[(size_t)tn * VV + lbl];
            float a  = A[prev][s];
            float bv = (s >= 1) ? A[prev][s - 1] : NEGV;
            float cv = sk ? A[prev][s - 2] : NEGV;
            float mx = fmaxf(a, fmaxf(bv, cv));
            float mn = fminf(a, fminf(bv, cv));
            float md = fmaxf(fminf(a, bv), fminf(fmaxf(a, bv), cv));
            float v  = mx + __logf(1.f + __expf(md - mx) + __expf(mn - mx));
            A[cur][s] = v + e_cur;
        }
        __syncthreads();
    }

    if (s == 0) {
        const int f = (len - 1) & 1;
        float l1 = A[f][2 * L - 1];
        float l2 = A[f][2 * L];
        float m = fmaxf(l1, l2);
        float last = m + logf(expf(l1 - m) + expf(l2 - m));
        float nll = (last > 0.5f * NEGV) ? -last : 0.f;
        g_loss[b] = nll / (float)len;
    }
}

__global__ __launch_bounds__(32) void k_reduce(float* __restrict__ out) {
    float v = g_loss[threadIdx.x];
#pragma unroll
    for (int o = 16; o > 0; o >>= 1) v += __shfl_xor_sync(0xffffffffu, v, o);
    if (threadIdx.x == 0) out[0] = v * (1.0f / BB);
}

// ---------------------------------------------------------------------------
extern "C" void kernel_launch(void* const* d_in, const int* in_sizes, int n_in,
                              void* d_out, int out_size) {
    const float* dec  = (const float*)d_in[0];
    const int*   tgt  = (const int*)d_in[1];
    const int*   dlen = (const int*)d_in[2];
    const int*   tlen = (const int*)d_in[3];
    const float* W1   = (const float*)d_in[4];
    const float* b1   = (const float*)d_in[5];
    const float* W2   = (const float*)d_in[6];
    const float* b2   = (const float*)d_in[7];
    float* out = (float*)d_out;

    const int SMEM1 = 164864;  // pad + 2 x 81920 stages (epilogue 133.6KB reuses)
    const int SMEM2 = 82944;   // pad + 2 x 40960 stages -> 2 CTAs/SM
    cudaFuncSetAttribute(k_gemm1, cudaFuncAttributeMaxDynamicSharedMemorySize, SMEM1);
    cudaFuncSetAttribute(k_gemm2, cudaFuncAttributeMaxDynamicSharedMemorySize, SMEM2);

    k_prep_dec<<<dim3(TP / 32, DD / 32, BB), dim3(32, 8)>>>(dec);
    k_prep_w1<<<dim3(DD / 32, DD / 32), dim3(32, 8)>>>(W1);
    k_prep_w2<<<(NTB * DD + 255) / 256, 256>>>(W2);

    k_gemm1<<<dim3(TP / 128, DD / 256, BB), 256, SMEM1>>>(dec, W1, b1);
    k_gemm2<<<dim3(TP / 128, BB), 256, SMEM2>>>(b2);

    k_ctc<<<BB, 448>>>(tgt, dlen, tlen);
    k_reduce<<<1, 32>>>(out);
}

// round 14
// speedup vs baseline: 1.6809x; 1.0207x over previous
#include <cuda_runtime.h>
#include <cuda_bf16.h>
#include <math.h>
#include <stdint.h>

#define BB 32
#define DD 1024
#define TT 1000
#define TP 1024
#define VV 80
#define NTB 96
#define LMAX 200
#define BLANK 79
#define NEGV (-1e30f)

#if defined(__CUDA_ARCH_FEAT_SM103_ALL) || defined(__CUDA_ARCH_FEAT_SM100_ALL)
#define HAS_TCGEN05 1
#else
#define HAS_TCGEN05 0
#endif

// ---------------- scratch ----------------------------------------------------
__device__ __nv_bfloat16 g_xh[(size_t)BB * TP * DD];   // dec bf16 (hi only)
__device__ __nv_bfloat16 g_w1h[(size_t)DD * DD];       // W1 hi, [e][d]
__device__ __nv_bfloat16 g_w1l[(size_t)DD * DD];       // W1 lo
__device__ __nv_bfloat16 g_w2h[(size_t)NTB * DD];      // W2 hi
__device__ __nv_bfloat16 g_w2l[(size_t)NTB * DD];      // W2 lo
__device__ __nv_bfloat16 g_hb[(size_t)BB * TP * DD];   // h bf16 (hi only)
__device__ float         g_lp[(size_t)BB * TT * VV];
__device__ float         g_loss[BB];

// ---------------- PTX helpers ------------------------------------------------
__device__ __forceinline__ uint32_t sm_u32(const void* p) {
    uint32_t a;
    asm("{ .reg .u64 t; cvta.to.shared.u64 t, %1; cvt.u32.u64 %0, t; }"
        : "=r"(a) : "l"(p));
    return a;
}
__device__ __forceinline__ bool elect1() {
    uint32_t p;
    asm volatile("{ .reg .pred p; elect.sync _|p, 0xFFFFFFFF; selp.b32 %0,1,0,p; }"
                 : "=r"(p));
    return p != 0;
}
__device__ __forceinline__ uint32_t swz(uint32_t off) { return off ^ ((off >> 3) & 0x70u); }
__device__ __forceinline__ uint64_t mkdesc(uint32_t addr) {
    const uint64_t base = (2ull << 61) | (1ull << 46) | (64ull << 32) | (1ull << 16);
    return base | (uint64_t)((addr >> 4) & 0x3FFF);
}
__device__ __forceinline__ void cp16(uint32_t dst, const void* src) {
    asm volatile("cp.async.cg.shared.global [%0], [%1], 16;" :: "r"(dst), "l"(src));
}
#define CP_COMMIT() asm volatile("cp.async.commit_group;" ::: "memory")
__device__ __forceinline__ void mbar_wait(uint32_t mbar, uint32_t parity) {
    asm volatile(
        "{\n\t.reg .pred P;\n\t"
        "WL%=:\n\t"
        "mbarrier.try_wait.parity.acquire.cta.shared::cta.b64 P, [%0], %1;\n\t"
        "@!P bra WL%=;\n\t}"
        :: "r"(mbar), "r"(parity) : "memory");
}

#if HAS_TCGEN05
__device__ __forceinline__ void mma_bf16_ss(uint32_t d, uint64_t ad, uint64_t bd,
                                            uint32_t idesc, bool acc) {
    uint32_t en = acc ? 1u : 0u;
    asm volatile(
        "{\n\t.reg .pred p;\n\t"
        "setp.ne.u32 p, %5, 0;\n\t"
        "tcgen05.mma.cta_group::1.kind::f16 [%0], %1, %2, %3, {%4,%4,%4,%4}, p;\n\t}"
        :: "r"(d), "l"(ad), "l"(bd), "r"(idesc), "r"(0u), "r"(en) : "memory");
}
#define LDTM_X32(r, a) asm volatile( \
    "tcgen05.ld.sync.aligned.32x32b.x32.b32 " \
    "{%0,%1,%2,%3,%4,%5,%6,%7,%8,%9,%10,%11,%12,%13,%14,%15," \
    "%16,%17,%18,%19,%20,%21,%22,%23,%24,%25,%26,%27,%28,%29,%30,%31}, [%32];" \
    : "=r"((r)[0]),"=r"((r)[1]),"=r"((r)[2]),"=r"((r)[3]), \
      "=r"((r)[4]),"=r"((r)[5]),"=r"((r)[6]),"=r"((r)[7]), \
      "=r"((r)[8]),"=r"((r)[9]),"=r"((r)[10]),"=r"((r)[11]), \
      "=r"((r)[12]),"=r"((r)[13]),"=r"((r)[14]),"=r"((r)[15]), \
      "=r"((r)[16]),"=r"((r)[17]),"=r"((r)[18]),"=r"((r)[19]), \
      "=r"((r)[20]),"=r"((r)[21]),"=r"((r)[22]),"=r"((r)[23]), \
      "=r"((r)[24]),"=r"((r)[25]),"=r"((r)[26]),"=r"((r)[27]), \
      "=r"((r)[28]),"=r"((r)[29]),"=r"((r)[30]),"=r"((r)[31]) \
    : "r"(a))
#define LDTM_X16(r, a) asm volatile( \
    "tcgen05.ld.sync.aligned.32x32b.x16.b32 " \
    "{%0,%1,%2,%3,%4,%5,%6,%7,%8,%9,%10,%11,%12,%13,%14,%15}, [%16];" \
    : "=r"((r)[0]),"=r"((r)[1]),"=r"((r)[2]),"=r"((r)[3]), \
      "=r"((r)[4]),"=r"((r)[5]),"=r"((r)[6]),"=r"((r)[7]), \
      "=r"((r)[8]),"=r"((r)[9]),"=r"((r)[10]),"=r"((r)[11]), \
      "=r"((r)[12]),"=r"((r)[13]),"=r"((r)[14]),"=r"((r)[15]) \
    : "r"(a))
#define TM_WAIT_LD() asm volatile("tcgen05.wait::ld.sync.aligned;" ::: "memory")
#endif

// ---------------- pre-passes -------------------------------------------------
__global__ __launch_bounds__(256) void k_prep_dec(const float* __restrict__ dec) {
    __shared__ float s[32][33];
    const int b = blockIdx.z, t0 = blockIdx.x * 32, d0 = blockIdx.y * 32;
    const int tx = threadIdx.x, ty = threadIdx.y;
    const float* in = dec + (size_t)b * DD * TT;
#pragma unroll
    for (int i = 0; i < 4; i++) {
        int d = d0 + ty + 8 * i, t = t0 + tx;
        s[ty + 8 * i][tx] = (t < TT) ? in[(size_t)d * TT + t] : 0.f;
    }
    __syncthreads();
#pragma unroll
    for (int i = 0; i < 4; i++) {
        int t = t0 + ty + 8 * i, d = d0 + tx;
        g_xh[(size_t)b * TP * DD + (size_t)t * DD + d] =
            __float2bfloat16_rn(s[tx][ty + 8 * i]);
    }
}
__global__ __launch_bounds__(256) void k_prep_w1(const float* __restrict__ W1) {
    __shared__ float s[32][33];
    const int e0 = blockIdx.x * 32, d0 = blockIdx.y * 32;
    const int tx = threadIdx.x, ty = threadIdx.y;
#pragma unroll
    for (int i = 0; i < 4; i++)
        s[ty + 8 * i][tx] = W1[(size_t)(d0 + ty + 8 * i) * DD + e0 + tx];
    __syncthreads();
#pragma unroll
    for (int i = 0; i < 4; i++) {
        float v = s[tx][ty + 8 * i];
        __nv_bfloat16 hi = __float2bfloat16_rn(v);
        __nv_bfloat16 lo = __float2bfloat16_rn(v - __bfloat162float(hi));
        size_t idx = (size_t)(e0 + ty + 8 * i) * DD + d0 + tx;
        g_w1h[idx] = hi;
        g_w1l[idx] = lo;
    }
}
__global__ __launch_bounds__(256) void k_prep_w2(const float* __restrict__ W2) {
    int idx = blockIdx.x * 256 + threadIdx.x;
    if (idx < NTB * DD) {
        int v = idx / DD, d = idx - v * DD;
        float x = (v < VV) ? W2[(size_t)d * VV + v] : 0.f;
        __nv_bfloat16 hi = __float2bfloat16_rn(x);
        __nv_bfloat16 lo = __float2bfloat16_rn(x - __bfloat162float(hi));
        g_w2h[idx] = hi;
        g_w2l[idx] = lo;
    }
}

// ---------------- GEMM1: 256x256 output block (2 M-tiles x 2 N-MMA), R6 pipe -
__global__ __launch_bounds__(256) void k_gemm1(const float* __restrict__ dec,
                                               const float* __restrict__ W1,
                                               const float* __restrict__ b1) {
    const int tid = threadIdx.x;
    const int b = blockIdx.z, m0 = blockIdx.x * 256, n0 = blockIdx.y * 256;

#if HAS_TCGEN05
    constexpr int ASZ = 16384;                // one 128x128B tile
    constexpr int STAGE = 2 * ASZ + 2 * 2 * ASZ;  // A0+A1 + Bh(2)+Bl(2) = 98304
    constexpr int NKB = DD / 64;              // 16
    extern __shared__ char dyn_raw[];
    __shared__ uint32_t s_tmem;
    __shared__ __align__(8) uint64_t s_mbar;

    const int wid = tid >> 5, lid = tid & 31;
    const uint32_t raw = sm_u32(dyn_raw);
    const uint32_t sb = (raw + 1023u) & ~1023u;
    char* dynsm = dyn_raw + (sb - raw);

    if (wid == 0) {
        asm volatile("tcgen05.alloc.cta_group::1.sync.aligned.shared::cta.b32 [%0], %1;"
                     :: "r"(sm_u32(&s_tmem)), "r"(512u) : "memory");
        asm volatile("tcgen05.relinquish_alloc_permit.cta_group::1.sync.aligned;");
        if (elect1())
            asm volatile("mbarrier.init.shared.b64 [%0], 1;"
                         :: "r"(sm_u32(&s_mbar)) : "memory");
    }
    __syncthreads();
    const uint32_t tmem = s_tmem;
    const uint32_t mbar = sm_u32(&s_mbar);

    const __nv_bfloat16* Ah = g_xh + (size_t)b * TP * DD + (size_t)m0 * DD;
    const __nv_bfloat16* Bh = g_w1h + (size_t)n0 * DD;
    const __nv_bfloat16* Bl = g_w1l + (size_t)n0 * DD;

    // stage layout: [A0 16K][A1 16K][Bh 32K][Bl 32K]
    auto ldstage = [&](int st, int kb) {
        const int k0 = kb * 64;
        const uint32_t su = sb + st * STAGE;
#pragma unroll
        for (int i = 0; i < 24; i++) {
            int c = tid + i * 256;   // 0..6143 (16B chunks)
            uint32_t dst;
            const __nv_bfloat16* src;
            if (c < 2048) {          // A rows 0..255 (A0 then A1, contiguous)
                int r = c >> 3, ch = c & 7;
                dst = su + swz((uint32_t)(r * 128 + ch * 16));
                src = Ah + (size_t)r * DD + k0 + ch * 8;
            } else if (c < 4096) {   // Bh rows 0..255
                int cc = c - 2048, r = cc >> 3, ch = cc & 7;
                dst = su + 2 * ASZ + swz((uint32_t)(r * 128 + ch * 16));
                src = Bh + (size_t)r * DD + k0 + ch * 8;
            } else {                 // Bl rows 0..255
                int cc = c - 4096, r = cc >> 3, ch = cc & 7;
                dst = su + 4 * ASZ + swz((uint32_t)(r * 128 + ch * 16));
                src = Bl + (size_t)r * DD + k0 + ch * 8;
            }
            cp16(dst, src);
        }
    };

    ldstage(0, 0);
    CP_COMMIT();

    const uint32_t idesc = (1u << 4) | (1u << 7) | (1u << 10) |
                           (16u << 17) | (8u << 24);   // N=128, M=128

    for (int kb = 0; kb < NKB; kb++) {
        const int st = kb & 1;
        if (kb + 1 < NKB) ldstage(st ^ 1, kb + 1);
        CP_COMMIT();
        asm volatile("cp.async.wait_group 1;" ::: "memory");
        __syncthreads();
        if (wid == 0) {
            asm volatile("fence.proxy.async.shared::cta;" ::: "memory");
            if (elect1()) {
                const uint32_t su = sb + st * STAGE;
                uint64_t a0  = mkdesc(su);
                uint64_t a1  = mkdesc(su + ASZ);
                uint64_t bh0 = mkdesc(su + 2 * ASZ);
                uint64_t bh1 = mkdesc(su + 3 * ASZ);
                uint64_t bl0 = mkdesc(su + 4 * ASZ);
                uint64_t bl1 = mkdesc(su + 5 * ASZ);
#pragma unroll
                for (int s4 = 0; s4 < 4; s4++) {
                    uint64_t o = 2 * s4;
                    bool first = (kb == 0 && s4 == 0);
                    mma_bf16_ss(tmem,       a0 + o, bh0 + o, idesc, !first);
                    mma_bf16_ss(tmem,       a0 + o, bl0 + o, idesc, true);
                    mma_bf16_ss(tmem + 128, a0 + o, bh1 + o, idesc, !first);
                    mma_bf16_ss(tmem + 128, a0 + o, bl1 + o, idesc, true);
                    mma_bf16_ss(tmem + 256, a1 + o, bh0 + o, idesc, !first);
                    mma_bf16_ss(tmem + 256, a1 + o, bl0 + o, idesc, true);
                    mma_bf16_ss(tmem + 384, a1 + o, bh1 + o, idesc, !first);
                    mma_bf16_ss(tmem + 384, a1 + o, bl1 + o, idesc, true);
                }
                asm volatile(
                    "tcgen05.commit.cta_group::1.mbarrier::arrive::one.shared::cluster.b64 [%0];"
                    :: "r"(mbar) : "memory");
            }
        }
        mbar_wait(mbar, (uint32_t)(kb & 1));
    }

    asm volatile("tcgen05.fence::after_thread_sync;" ::: "memory");
    __syncthreads();

    // epilogue: per m-tile, TMEM(256 cols) -> smem fp32 -> bias+relu -> bf16
    float* sh = (float*)dynsm;  // stride 261 floats, 128 rows (133.6KB)
#pragma unroll
    for (int mt = 0; mt < 2; mt++) {
        if (wid < 4) {
            const int row = wid * 32 + lid;
#pragma unroll
            for (int c4 = 0; c4 < 8; c4++) {
                uint32_t r[32];
                LDTM_X32(r, tmem + mt * 256 + c4 * 32);
                TM_WAIT_LD();
#pragma unroll
                for (int j = 0; j < 32; j++)
                    sh[row * 261 + c4 * 32 + j] = __uint_as_float(r[j]);
            }
            asm volatile("tcgen05.fence::before_thread_sync;" ::: "memory");
        }
        __syncthreads();
#pragma unroll 4
        for (int i = 0; i < 64; i++) {
            int idx = tid + i * 256;               // pair idx over 128x128
            int r = idx >> 7, cp2 = (idx & 127) * 2;
            float v0 = fmaxf(sh[r * 261 + cp2] + b1[n0 + cp2], 0.f);
            float v1 = fmaxf(sh[r * 261 + cp2 + 1] + b1[n0 + cp2 + 1], 0.f);
            *reinterpret_cast<__nv_bfloat162*>(
                &g_hb[((size_t)b * TP + m0 + mt * 128 + r) * DD + n0 + cp2]) =
                __floats2bfloat162_rn(v0, v1);
        }
        __syncthreads();
    }
    if (wid == 0)
        asm volatile("tcgen05.dealloc.cta_group::1.sync.aligned.b32 %0, %1;"
                     :: "r"(tmem), "r"(512u));

#else  // SIMT fallback (compile-only on non-103a pass)
    __shared__ float As[16][128];
    __shared__ float Bs[16][128];
    const int tx = tid & 15, ty = tid >> 4;
    const float* A = dec + (size_t)b * DD * TT;
    for (int mh = 0; mh < 2; mh++) {
        const int m0h = m0 + mh * 128;
        for (int nh = 0; nh < 2; nh++) {
            const int n0h = n0 + nh * 128;
            float acc[8][8];
#pragma unroll
            for (int i = 0; i < 8; i++)
#pragma unroll
                for (int j = 0; j < 8; j++) acc[i][j] = 0.f;
            for (int k0 = 0; k0 < DD; k0 += 16) {
                __syncthreads();
#pragma unroll
                for (int i = 0; i < 8; i++) {
                    int idx = tid + i * 256;
                    int kk = idx >> 7, mm = idx & 127;
                    int m = m0h + mm;
                    As[kk][mm] = (m < TT) ? A[(size_t)(k0 + kk) * TT + m] : 0.f;
                    Bs[kk][mm] = W1[(size_t)(k0 + kk) * DD + n0h + mm];
                }
                __syncthreads();
#pragma unroll
                for (int kk = 0; kk < 16; kk++) {
                    float a[8], w[8];
#pragma unroll
                    for (int i = 0; i < 8; i++) a[i] = As[kk][ty * 8 + i];
#pragma unroll
                    for (int j = 0; j < 8; j++) w[j] = Bs[kk][tx * 8 + j];
#pragma unroll
                    for (int i = 0; i < 8; i++)
#pragma unroll
                        for (int j = 0; j < 8; j++)
                            acc[i][j] = fmaf(a[i], w[j], acc[i][j]);
                }
            }
#pragma unroll
            for (int i = 0; i < 8; i++) {
                int m = m0h + ty * 8 + i;
#pragma unroll
                for (int j = 0; j < 8; j++) {
                    int n = n0h + tx * 8 + j;
                    g_hb[((size_t)b * TP + m) * DD + n] =
                        __float2bfloat16_rn(fmaxf(acc[i][j] + b1[n], 0.f));
                }
            }
            __syncthreads();
        }
    }
#endif
}

// ---------------- GEMM2 + fused softmax, A-hi only + W split -----------------
__global__ __launch_bounds__(256) void k_gemm2(const float* __restrict__ b2) {
    const int tid = threadIdx.x;
    const int b = blockIdx.y, m0 = blockIdx.x * 128;

#if HAS_TCGEN05
    constexpr int ASZ = 16384;
    constexpr int BSZ = NTB * 128;            // 12288
    constexpr int STAGE = ASZ + 2 * BSZ;      // 40960
    constexpr int NKB = DD / 64;
    extern __shared__ char dyn_raw[];
    __shared__ uint32_t s_tmem;
    __shared__ __align__(8) uint64_t s_mbar;

    const int wid = tid >> 5, lid = tid & 31;
    const uint32_t raw = sm_u32(dyn_raw);
    const uint32_t sb = (raw + 1023u) & ~1023u;
    char* dynsm = dyn_raw + (sb - raw);

    if (wid == 0) {
        asm volatile("tcgen05.alloc.cta_group::1.sync.aligned.shared::cta.b32 [%0], %1;"
                     :: "r"(sm_u32(&s_tmem)), "r"(128u) : "memory");
        asm volatile("tcgen05.relinquish_alloc_permit.cta_group::1.sync.aligned;");
        if (elect1())
            asm volatile("mbarrier.init.shared.b64 [%0], 1;"
                         :: "r"(sm_u32(&s_mbar)) : "memory");
    }
    __syncthreads();
    const uint32_t tmem = s_tmem;
    const uint32_t mbar = sm_u32(&s_mbar);

    const __nv_bfloat16* Ah = g_hb + (size_t)b * TP * DD + (size_t)m0 * DD;

    auto ldstage = [&](int st, int kb) {
        const int k0 = kb * 64;
        const uint32_t su = sb + st * STAGE;
#pragma unroll
        for (int i = 0; i < 10; i++) {
            int c = tid + i * 256;   // 0..2559
            uint32_t dst;
            const __nv_bfloat16* src;
            if (c < 1024) {
                int r = c >> 3, ch = c & 7;
                dst = su + swz((uint32_t)(r * 128 + ch * 16));
                src = Ah + (size_t)r * DD + k0 + ch * 8;
            } else if (c < 1792) {
                int cc = c - 1024, r = cc >> 3, ch = cc & 7;   // r 0..95
                dst = su + ASZ + swz((uint32_t)(r * 128 + ch * 16));
                src = g_w2h + (size_t)r * DD + k0 + ch * 8;
            } else {
                int cc = c - 1792, r = cc >> 3, ch = cc & 7;
                dst = su + ASZ + BSZ + swz((uint32_t)(r * 128 + ch * 16));
                src = g_w2l + (size_t)r * DD + k0 + ch * 8;
            }
            cp16(dst, src);
        }
    };

    ldstage(0, 0);
    CP_COMMIT();

    const uint32_t idesc = (1u << 4) | (1u << 7) | (1u << 10) |
                           ((uint32_t)(NTB / 8) << 17) | (8u << 24);

    for (int kb = 0; kb < NKB; kb++) {
        const int st = kb & 1;
        if (kb + 1 < NKB) ldstage(st ^ 1, kb + 1);
        CP_COMMIT();
        asm volatile("cp.async.wait_group 1;" ::: "memory");
        __syncthreads();
        if (wid == 0) {
            asm volatile("fence.proxy.async.shared::cta;" ::: "memory");
            if (elect1()) {
                const uint32_t su = sb + st * STAGE;
                uint64_t ah = mkdesc(su);
                uint64_t bh = mkdesc(su + ASZ);
                uint64_t bl = mkdesc(su + ASZ + BSZ);
#pragma unroll
                for (int s4 = 0; s4 < 4; s4++) {
                    uint64_t o = 2 * s4;
                    mma_bf16_ss(tmem, ah + o, bh + o, idesc, !(kb == 0 && s4 == 0));
                    mma_bf16_ss(tmem, ah + o, bl + o, idesc, true);
                }
                asm volatile(
                    "tcgen05.commit.cta_group::1.mbarrier::arrive::one.shared::cluster.b64 [%0];"
                    :: "r"(mbar) : "memory");
            }
        }
        mbar_wait(mbar, (uint32_t)(kb & 1));
    }

    asm volatile("tcgen05.fence::after_thread_sync;" ::: "memory");
    __syncthreads();

    float* sh = (float*)dynsm;  // [128][81]
    if (wid < 4) {
        float v[VV];
        {
            uint32_t r[32];
            LDTM_X32(r, tmem);
            TM_WAIT_LD();
#pragma unroll
            for (int j = 0; j < 32; j++) v[j] = __uint_as_float(r[j]);
        }
        {
            uint32_t r[32];
            LDTM_X32(r, tmem + 32);
            TM_WAIT_LD();
#pragma unroll
            for (int j = 0; j < 32; j++) v[32 + j] = __uint_as_float(r[j]);
        }
        {
            uint32_t r[16];
            LDTM_X16(r, tmem + 64);
            TM_WAIT_LD();
#pragma unroll
            for (int j = 0; j < 16; j++) v[64 + j] = __uint_as_float(r[j]);
        }
        asm volatile("tcgen05.fence::before_thread_sync;" ::: "memory");
        float mx = -1e30f;
#pragma unroll
        for (int j = 0; j < VV; j++) { v[j] += b2[j]; mx = fmaxf(mx, v[j]); }
        float sum = 0.f;
#pragma unroll
        for (int j = 0; j < VV; j++) sum += expf(v[j] - mx);
        const float lse = mx + logf(sum);
        const int row = wid * 32 + lid;
#pragma unroll
        for (int j = 0; j < VV; j++) sh[row * 81 + j] = v[j] - lse;
    }
    __syncthreads();
#pragma unroll 4
    for (int i = 0; i < 40; i++) {
        int idx = tid + i * 256;
        int rr = idx / 80, cc = idx - rr * 80;
        int t = m0 + rr;
        if (t < TT) g_lp[((size_t)b * TT + t) * VV + cc] = sh[rr * 81 + cc];
    }
    __syncthreads();
    if (wid == 0)
        asm volatile("tcgen05.dealloc.cta_group::1.sync.aligned.b32 %0, %1;"
                     :: "r"(tmem), "r"(128u));

#else  // SIMT fallback (compile-only)
    const int r = m0 + (tid & 127);
    if (tid < 128) {
        float v[VV];
        for (int j = 0; j < VV; j++) v[j] = b2[j];
        const __nv_bfloat16* hh = g_hb + ((size_t)b * TP + r) * DD;
        for (int k = 0; k < DD; k++) {
            float hv = __bfloat162float(hh[k]);
            for (int j = 0; j < VV; j++)
                v[j] = fmaf(hv, __bfloat162float(g_w2h[(size_t)j * DD + k]) +
                                 __bfloat162float(g_w2l[(size_t)j * DD + k]), v[j]);
        }
        float mx = -1e30f;
        for (int j = 0; j < VV; j++) mx = fmaxf(mx, v[j]);
        float sum = 0.f;
        for (int j = 0; j < VV; j++) sum += expf(v[j] - mx);
        float lse = mx + logf(sum);
        if (r < TT)
            for (int j = 0; j < VV; j++)
                g_lp[((size_t)b * TT + r) * VV + j] = v[j] - lse;
    }
#endif
}

// ---------------- CTC DP: median-trick lse3 + early-exit + reg prefetch ------
__global__ __launch_bounds__(448) void k_ctc(const int* __restrict__ tgt,
                                             const int* __restrict__ dlen,
                                             const int* __restrict__ tlen) {
    const int b = blockIdx.x;
    const int L = tlen[b];
    const int S = 2 * L + 1;
    const int len = dlen[b];
    const int s = threadIdx.x;

    if (s >= ((S + 31) & ~31)) return;  // retire unused warps entirely

    __shared__ float A[2][2 * LMAX + 1];
    __shared__ int ext[2 * LMAX + 1];

    const float* lpb = g_lp + (size_t)b * TT * VV;

    int lbl = BLANK;
    if (s < S) {
        lbl = (s & 1) ? tgt[b * LMAX + (s >> 1)] : BLANK;
        ext[s] = lbl;
    }
    __syncthreads();
    bool sk = false;
    if (s < S) {
        sk = ((s & 1) && s >= 3 && lbl != ext[s - 2]);
        float a0 = NEGV;
        if (s == 0)      a0 = lpb[BLANK];
        else if (s == 1) a0 = lpb[lbl];
        A[0][s] = a0;
    }

    float eA = 0.f, eB = 0.f;
    if (s < S) {
        int t1 = (1 < len) ? 1 : len - 1;
        int t2 = (2 < len) ? 2 : len - 1;
        eA = lpb[(size_t)t1 * VV + lbl];
        eB = lpb[(size_t)t2 * VV + lbl];
    }
    __syncthreads();

    for (int t = 1; t < len; t++) {
        const int cur = t & 1, prev = cur ^ 1;
        float e_cur = eA;
        eA = eB;
        if (s < S) {
            int tn = (t + 2 < len) ? t + 2 : len - 1;
            eB = lpb[(size_t)tn * VV + lbl];
            float a  = A[prev][s];
            float bv = (s >= 1) ? A[prev][s - 1] : NEGV;
            float cv = sk ? A[prev][s - 2] : NEGV;
            float mx = fmaxf(a, fmaxf(bv, cv));
            float mn = fminf(a, fminf(bv, cv));
            float md = fmaxf(fminf(a, bv), fminf(fmaxf(a, bv), cv));
            float v  = mx + __logf(1.f + __expf(md - mx) + __expf(mn - mx));
            A[cur][s] = v + e_cur;
        }
        __syncthreads();
    }

    if (s == 0) {
        const int f = (len - 1) & 1;
        float l1 = A[f][2 * L - 1];
        float l2 = A[f][2 * L];
        float m = fmaxf(l1, l2);
        float last = m + logf(expf(l1 - m) + expf(l2 - m));
        float nll = (last > 0.5f * NEGV) ? -last : 0.f;
        g_loss[b] = nll / (float)len;
    }
}

__global__ __launch_bounds__(32) void k_reduce(float* __restrict__ out) {
    float v = g_loss[threadIdx.x];
#pragma unroll
    for (int o = 16; o > 0; o >>= 1) v += __shfl_xor_sync(0xffffffffu, v, o);
    if (threadIdx.x == 0) out[0] = v * (1.0f / BB);
}

// ---------------------------------------------------------------------------
extern "C" void kernel_launch(void* const* d_in, const int* in_sizes, int n_in,
                              void* d_out, int out_size) {
    const float* dec  = (const float*)d_in[0];
    const int*   tgt  = (const int*)d_in[1];
    const int*   dlen = (const int*)d_in[2];
    const int*   tlen = (const int*)d_in[3];
    const float* W1   = (const float*)d_in[4];
    const float* b1   = (const float*)d_in[5];
    const float* W2   = (const float*)d_in[6];
    const float* b2   = (const float*)d_in[7];
    float* out = (float*)d_out;

    const int SMEM1 = 197632;  // pad + 2 x 98304 stages (epilogue 133.6KB reuses)
    const int SMEM2 = 82944;   // pad + 2 x 40960 stages -> 2 CTAs/SM
    cudaFuncSetAttribute(k_gemm1, cudaFuncAttributeMaxDynamicSharedMemorySize, SMEM1);
    cudaFuncSetAttribute(k_gemm2, cudaFuncAttributeMaxDynamicSharedMemorySize, SMEM2);

    k_prep_dec<<<dim3(TP / 32, DD / 32, BB), dim3(32, 8)>>>(dec);
    k_prep_w1<<<dim3(DD / 32, DD / 32), dim3(32, 8)>>>(W1);
    k_prep_w2<<<(NTB * DD + 255) / 256, 256>>>(W2);

    k_gemm1<<<dim3(TP / 256, DD / 256, BB), 256, SMEM1>>>(dec, W1, b1);
    k_gemm2<<<dim3(TP / 128, BB), 256, SMEM2>>>(b2);

    k_ctc<<<BB, 448>>>(tgt, dlen, tlen);
    k_reduce<<<1, 32>>>(out);
}

// round 16
// speedup vs baseline: 2.1252x; 1.2643x over previous
#include <cuda_runtime.h>
#include <cuda_bf16.h>
#include <math.h>
#include <stdint.h>

#define BB 32
#define DD 1024
#define TT 1000
#define TP 1024
#define VV 80
#define NTB 96
#define LMAX 200
#define BLANK 79
#define NEGV (-1e30f)

#if defined(__CUDA_ARCH_FEAT_SM103_ALL) || defined(__CUDA_ARCH_FEAT_SM100_ALL)
#define HAS_TCGEN05 1
#else
#define HAS_TCGEN05 0
#endif

// ---------------- scratch ----------------------------------------------------
__device__ __nv_bfloat16 g_xh[(size_t)BB * TP * DD];   // dec bf16 (hi only)
__device__ __nv_bfloat16 g_w1h[(size_t)DD * DD];       // W1 hi, [e][d]
__device__ __nv_bfloat16 g_w1l[(size_t)DD * DD];       // W1 lo
__device__ __nv_bfloat16 g_w2h[(size_t)NTB * DD];      // W2 hi
__device__ __nv_bfloat16 g_w2l[(size_t)NTB * DD];      // W2 lo
__device__ __nv_bfloat16 g_hb[(size_t)BB * TP * DD];   // h bf16 (hi only)
__device__ float         g_lp[(size_t)BB * TT * VV];
__device__ float         g_loss[BB];

// ---------------- PTX helpers ------------------------------------------------
__device__ __forceinline__ uint32_t sm_u32(const void* p) {
    uint32_t a;
    asm("{ .reg .u64 t; cvta.to.shared.u64 t, %1; cvt.u32.u64 %0, t; }"
        : "=r"(a) : "l"(p));
    return a;
}
__device__ __forceinline__ bool elect1() {
    uint32_t p;
    asm volatile("{ .reg .pred p; elect.sync _|p, 0xFFFFFFFF; selp.b32 %0,1,0,p; }"
                 : "=r"(p));
    return p != 0;
}
__device__ __forceinline__ uint32_t swz(uint32_t off) { return off ^ ((off >> 3) & 0x70u); }
__device__ __forceinline__ uint64_t mkdesc(uint32_t addr) {
    const uint64_t base = (2ull << 61) | (1ull << 46) | (64ull << 32) | (1ull << 16);
    return base | (uint64_t)((addr >> 4) & 0x3FFF);
}
__device__ __forceinline__ void cp16(uint32_t dst, const void* src) {
    asm volatile("cp.async.cg.shared.global [%0], [%1], 16;" :: "r"(dst), "l"(src));
}
#define CP_COMMIT() asm volatile("cp.async.commit_group;" ::: "memory")
__device__ __forceinline__ void mbar_wait(uint32_t mbar, uint32_t parity) {
    asm volatile(
        "{\n\t.reg .pred P;\n\t"
        "WL%=:\n\t"
        "mbarrier.try_wait.parity.acquire.cta.shared::cta.b64 P, [%0], %1;\n\t"
        "@!P bra WL%=;\n\t}"
        :: "r"(mbar), "r"(parity) : "memory");
}

#if HAS_TCGEN05
__device__ __forceinline__ void mma_bf16_ss(uint32_t d, uint64_t ad, uint64_t bd,
                                            uint32_t idesc, bool acc) {
    uint32_t en = acc ? 1u : 0u;
    asm volatile(
        "{\n\t.reg .pred p;\n\t"
        "setp.ne.u32 p, %5, 0;\n\t"
        "tcgen05.mma.cta_group::1.kind::f16 [%0], %1, %2, %3, {%4,%4,%4,%4}, p;\n\t}"
        :: "r"(d), "l"(ad), "l"(bd), "r"(idesc), "r"(0u), "r"(en) : "memory");
}
#define LDTM_X32(r, a) asm volatile( \
    "tcgen05.ld.sync.aligned.32x32b.x32.b32 " \
    "{%0,%1,%2,%3,%4,%5,%6,%7,%8,%9,%10,%11,%12,%13,%14,%15," \
    "%16,%17,%18,%19,%20,%21,%22,%23,%24,%25,%26,%27,%28,%29,%30,%31}, [%32];" \
    : "=r"((r)[0]),"=r"((r)[1]),"=r"((r)[2]),"=r"((r)[3]), \
      "=r"((r)[4]),"=r"((r)[5]),"=r"((r)[6]),"=r"((r)[7]), \
      "=r"((r)[8]),"=r"((r)[9]),"=r"((r)[10]),"=r"((r)[11]), \
      "=r"((r)[12]),"=r"((r)[13]),"=r"((r)[14]),"=r"((r)[15]), \
      "=r"((r)[16]),"=r"((r)[17]),"=r"((r)[18]),"=r"((r)[19]), \
      "=r"((r)[20]),"=r"((r)[21]),"=r"((r)[22]),"=r"((r)[23]), \
      "=r"((r)[24]),"=r"((r)[25]),"=r"((r)[26]),"=r"((r)[27]), \
      "=r"((r)[28]),"=r"((r)[29]),"=r"((r)[30]),"=r"((r)[31]) \
    : "r"(a))
#define LDTM_X16(r, a) asm volatile( \
    "tcgen05.ld.sync.aligned.32x32b.x16.b32 " \
    "{%0,%1,%2,%3,%4,%5,%6,%7,%8,%9,%10,%11,%12,%13,%14,%15}, [%16];" \
    : "=r"((r)[0]),"=r"((r)[1]),"=r"((r)[2]),"=r"((r)[3]), \
      "=r"((r)[4]),"=r"((r)[5]),"=r"((r)[6]),"=r"((r)[7]), \
      "=r"((r)[8]),"=r"((r)[9]),"=r"((r)[10]),"=r"((r)[11]), \
      "=r"((r)[12]),"=r"((r)[13]),"=r"((r)[14]),"=r"((r)[15]) \
    : "r"(a))
#define TM_WAIT_LD() asm volatile("tcgen05.wait::ld.sync.aligned;" ::: "memory")
#endif

// ---------------- pre-passes -------------------------------------------------
__global__ __launch_bounds__(256) void k_prep_dec(const float* __restrict__ dec) {
    __shared__ float s[32][33];
    const int b = blockIdx.z, t0 = blockIdx.x * 32, d0 = blockIdx.y * 32;
    const int tx = threadIdx.x, ty = threadIdx.y;
    const float* in = dec + (size_t)b * DD * TT;
#pragma unroll
    for (int i = 0; i < 4; i++) {
        int d = d0 + ty + 8 * i, t = t0 + tx;
        s[ty + 8 * i][tx] = (t < TT) ? in[(size_t)d * TT + t] : 0.f;
    }
    __syncthreads();
#pragma unroll
    for (int i = 0; i < 4; i++) {
        int t = t0 + ty + 8 * i, d = d0 + tx;
        g_xh[(size_t)b * TP * DD + (size_t)t * DD + d] =
            __float2bfloat16_rn(s[tx][ty + 8 * i]);
    }
}
__global__ __launch_bounds__(256) void k_prep_w1(const float* __restrict__ W1) {
    __shared__ float s[32][33];
    const int e0 = blockIdx.x * 32, d0 = blockIdx.y * 32;
    const int tx = threadIdx.x, ty = threadIdx.y;
#pragma unroll
    for (int i = 0; i < 4; i++)
        s[ty + 8 * i][tx] = W1[(size_t)(d0 + ty + 8 * i) * DD + e0 + tx];
    __syncthreads();
#pragma unroll
    for (int i = 0; i < 4; i++) {
        float v = s[tx][ty + 8 * i];
        __nv_bfloat16 hi = __float2bfloat16_rn(v);
        __nv_bfloat16 lo = __float2bfloat16_rn(v - __bfloat162float(hi));
        size_t idx = (size_t)(e0 + ty + 8 * i) * DD + d0 + tx;
        g_w1h[idx] = hi;
        g_w1l[idx] = lo;
    }
}
__global__ __launch_bounds__(256) void k_prep_w2(const float* __restrict__ W2) {
    int idx = blockIdx.x * 256 + threadIdx.x;
    if (idx < NTB * DD) {
        int v = idx / DD, d = idx - v * DD;
        float x = (v < VV) ? W2[(size_t)d * VV + v] : 0.f;
        __nv_bfloat16 hi = __float2bfloat16_rn(x);
        __nv_bfloat16 lo = __float2bfloat16_rn(x - __bfloat162float(hi));
        g_w2h[idx] = hi;
        g_w2l[idx] = lo;
    }
}

// ---------------- GEMM1: 256x256 output block (2 M-tiles x 2 N-MMA), R6 pipe -
__global__ __launch_bounds__(256) void k_gemm1(const float* __restrict__ dec,
                                               const float* __restrict__ W1,
                                               const float* __restrict__ b1) {
    const int tid = threadIdx.x;
    const int b = blockIdx.z, m0 = blockIdx.x * 256, n0 = blockIdx.y * 256;

#if HAS_TCGEN05
    constexpr int ASZ = 16384;                // one 128x128B tile
    constexpr int STAGE = 2 * ASZ + 2 * 2 * ASZ;  // A0+A1 + Bh(2)+Bl(2) = 98304
    constexpr int NKB = DD / 64;              // 16
    extern __shared__ char dyn_raw[];
    __shared__ uint32_t s_tmem;
    __shared__ __align__(8) uint64_t s_mbar;

    const int wid = tid >> 5, lid = tid & 31;
    const uint32_t raw = sm_u32(dyn_raw);
    const uint32_t sb = (raw + 1023u) & ~1023u;
    char* dynsm = dyn_raw + (sb - raw);

    if (wid == 0) {
        asm volatile("tcgen05.alloc.cta_group::1.sync.aligned.shared::cta.b32 [%0], %1;"
                     :: "r"(sm_u32(&s_tmem)), "r"(512u) : "memory");
        asm volatile("tcgen05.relinquish_alloc_permit.cta_group::1.sync.aligned;");
        if (elect1())
            asm volatile("mbarrier.init.shared.b64 [%0], 1;"
                         :: "r"(sm_u32(&s_mbar)) : "memory");
    }
    __syncthreads();
    const uint32_t tmem = s_tmem;
    const uint32_t mbar = sm_u32(&s_mbar);

    const __nv_bfloat16* Ah = g_xh + (size_t)b * TP * DD + (size_t)m0 * DD;
    const __nv_bfloat16* Bh = g_w1h + (size_t)n0 * DD;
    const __nv_bfloat16* Bl = g_w1l + (size_t)n0 * DD;

    // stage layout: [A0 16K][A1 16K][Bh 32K][Bl 32K]
    auto ldstage = [&](int st, int kb) {
        const int k0 = kb * 64;
        const uint32_t su = sb + st * STAGE;
#pragma unroll
        for (int i = 0; i < 24; i++) {
            int c = tid + i * 256;   // 0..6143 (16B chunks)
            uint32_t dst;
            const __nv_bfloat16* src;
            if (c < 2048) {          // A rows 0..255
                int r = c >> 3, ch = c & 7;
                dst = su + swz((uint32_t)(r * 128 + ch * 16));
                src = Ah + (size_t)r * DD + k0 + ch * 8;
            } else if (c < 4096) {   // Bh rows 0..255
                int cc = c - 2048, r = cc >> 3, ch = cc & 7;
                dst = su + 2 * ASZ + swz((uint32_t)(r * 128 + ch * 16));
                src = Bh + (size_t)r * DD + k0 + ch * 8;
            } else {                 // Bl rows 0..255
                int cc = c - 4096, r = cc >> 3, ch = cc & 7;
                dst = su + 4 * ASZ + swz((uint32_t)(r * 128 + ch * 16));
                src = Bl + (size_t)r * DD + k0 + ch * 8;
            }
            cp16(dst, src);
        }
    };

    ldstage(0, 0);
    CP_COMMIT();

    const uint32_t idesc = (1u << 4) | (1u << 7) | (1u << 10) |
                           (16u << 17) | (8u << 24);   // N=128, M=128

    for (int kb = 0; kb < NKB; kb++) {
        const int st = kb & 1;
        if (kb + 1 < NKB) ldstage(st ^ 1, kb + 1);
        CP_COMMIT();
        asm volatile("cp.async.wait_group 1;" ::: "memory");
        __syncthreads();
        if (wid == 0) {
            asm volatile("fence.proxy.async.shared::cta;" ::: "memory");
            if (elect1()) {
                const uint32_t su = sb + st * STAGE;
                uint64_t a0  = mkdesc(su);
                uint64_t a1  = mkdesc(su + ASZ);
                uint64_t bh0 = mkdesc(su + 2 * ASZ);
                uint64_t bh1 = mkdesc(su + 3 * ASZ);
                uint64_t bl0 = mkdesc(su + 4 * ASZ);
                uint64_t bl1 = mkdesc(su + 5 * ASZ);
#pragma unroll
                for (int s4 = 0; s4 < 4; s4++) {
                    uint64_t o = 2 * s4;
                    bool first = (kb == 0 && s4 == 0);
                    mma_bf16_ss(tmem,       a0 + o, bh0 + o, idesc, !first);
                    mma_bf16_ss(tmem,       a0 + o, bl0 + o, idesc, true);
                    mma_bf16_ss(tmem + 128, a0 + o, bh1 + o, idesc, !first);
                    mma_bf16_ss(tmem + 128, a0 + o, bl1 + o, idesc, true);
                    mma_bf16_ss(tmem + 256, a1 + o, bh0 + o, idesc, !first);
                    mma_bf16_ss(tmem + 256, a1 + o, bl0 + o, idesc, true);
                    mma_bf16_ss(tmem + 384, a1 + o, bh1 + o, idesc, !first);
                    mma_bf16_ss(tmem + 384, a1 + o, bl1 + o, idesc, true);
                }
                asm volatile(
                    "tcgen05.commit.cta_group::1.mbarrier::arrive::one.shared::cluster.b64 [%0];"
                    :: "r"(mbar) : "memory");
            }
        }
        mbar_wait(mbar, (uint32_t)(kb & 1));
    }

    asm volatile("tcgen05.fence::after_thread_sync;" ::: "memory");
    __syncthreads();

    // epilogue: per m-tile, TMEM(256 cols) -> smem fp32 -> bias+relu -> bf16
    float* sh = (float*)dynsm;  // stride 261 floats, 128 rows (133.6KB)
#pragma unroll
    for (int mt = 0; mt < 2; mt++) {
        if (wid < 4) {
            const int row = wid * 32 + lid;
#pragma unroll
            for (int c4 = 0; c4 < 8; c4++) {
                uint32_t r[32];
                LDTM_X32(r, tmem + mt * 256 + c4 * 32);
                TM_WAIT_LD();
#pragma unroll
                for (int j = 0; j < 32; j++)
                    sh[row * 261 + c4 * 32 + j] = __uint_as_float(r[j]);
            }
            asm volatile("tcgen05.fence::before_thread_sync;" ::: "memory");
        }
        __syncthreads();
#pragma unroll 4
        for (int i = 0; i < 64; i++) {
            int idx = tid + i * 256;               // pair idx over 128x128
            int r = idx >> 7, cp2 = (idx & 127) * 2;
            float v0 = fmaxf(sh[r * 261 + cp2] + b1[n0 + cp2], 0.f);
            float v1 = fmaxf(sh[r * 261 + cp2 + 1] + b1[n0 + cp2 + 1], 0.f);
            *reinterpret_cast<__nv_bfloat162*>(
                &g_hb[((size_t)b * TP + m0 + mt * 128 + r) * DD + n0 + cp2]) =
                __floats2bfloat162_rn(v0, v1);
        }
        __syncthreads();
    }
    if (wid == 0)
        asm volatile("tcgen05.dealloc.cta_group::1.sync.aligned.b32 %0, %1;"
                     :: "r"(tmem), "r"(512u));

#else  // SIMT fallback (compile-only on non-103a pass)
    __shared__ float As[16][128];
    __shared__ float Bs[16][128];
    const int tx = tid & 15, ty = tid >> 4;
    const float* A = dec + (size_t)b * DD * TT;
    for (int mh = 0; mh < 2; mh++) {
        const int m0h = m0 + mh * 128;
        for (int nh = 0; nh < 2; nh++) {
            const int n0h = n0 + nh * 128;
            float acc[8][8];
#pragma unroll
            for (int i = 0; i < 8; i++)
#pragma unroll
                for (int j = 0; j < 8; j++) acc[i][j] = 0.f;
            for (int k0 = 0; k0 < DD; k0 += 16) {
                __syncthreads();
#pragma unroll
                for (int i = 0; i < 8; i++) {
                    int idx = tid + i * 256;
                    int kk = idx >> 7, mm = idx & 127;
                    int m = m0h + mm;
                    As[kk][mm] = (m < TT) ? A[(size_t)(k0 + kk) * TT + m] : 0.f;
                    Bs[kk][mm] = W1[(size_t)(k0 + kk) * DD + n0h + mm];
                }
                __syncthreads();
#pragma unroll
                for (int kk = 0; kk < 16; kk++) {
                    float a[8], w[8];
#pragma unroll
                    for (int i = 0; i < 8; i++) a[i] = As[kk][ty * 8 + i];
#pragma unroll
                    for (int j = 0; j < 8; j++) w[j] = Bs[kk][tx * 8 + j];
#pragma unroll
                    for (int i = 0; i < 8; i++)
#pragma unroll
                        for (int j = 0; j < 8; j++)
                            acc[i][j] = fmaf(a[i], w[j], acc[i][j]);
                }
            }
#pragma unroll
            for (int i = 0; i < 8; i++) {
                int m = m0h + ty * 8 + i;
#pragma unroll
                for (int j = 0; j < 8; j++) {
                    int n = n0h + tx * 8 + j;
                    g_hb[((size_t)b * TP + m) * DD + n] =
                        __float2bfloat16_rn(fmaxf(acc[i][j] + b1[n], 0.f));
                }
            }
            __syncthreads();
        }
    }
#endif
}

// ---------------- GEMM2 + fused softmax, A-hi only + W split -----------------
__global__ __launch_bounds__(256) void k_gemm2(const float* __restrict__ b2) {
    const int tid = threadIdx.x;
    const int b = blockIdx.y, m0 = blockIdx.x * 128;

#if HAS_TCGEN05
    constexpr int ASZ = 16384;
    constexpr int BSZ = NTB * 128;            // 12288
    constexpr int STAGE = ASZ + 2 * BSZ;      // 40960
    constexpr int NKB = DD / 64;
    extern __shared__ char dyn_raw[];
    __shared__ uint32_t s_tmem;
    __shared__ __align__(8) uint64_t s_mbar;

    const int wid = tid >> 5, lid = tid & 31;
    const uint32_t raw = sm_u32(dyn_raw);
    const uint32_t sb = (raw + 1023u) & ~1023u;
    char* dynsm = dyn_raw + (sb - raw);

    if (wid == 0) {
        asm volatile("tcgen05.alloc.cta_group::1.sync.aligned.shared::cta.b32 [%0], %1;"
                     :: "r"(sm_u32(&s_tmem)), "r"(128u) : "memory");
        asm volatile("tcgen05.relinquish_alloc_permit.cta_group::1.sync.aligned;");
        if (elect1())
            asm volatile("mbarrier.init.shared.b64 [%0], 1;"
                         :: "r"(sm_u32(&s_mbar)) : "memory");
    }
    __syncthreads();
    const uint32_t tmem = s_tmem;
    const uint32_t mbar = sm_u32(&s_mbar);

    const __nv_bfloat16* Ah = g_hb + (size_t)b * TP * DD + (size_t)m0 * DD;

    auto ldstage = [&](int st, int kb) {
        const int k0 = kb * 64;
        const uint32_t su = sb + st * STAGE;
#pragma unroll
        for (int i = 0; i < 10; i++) {
            int c = tid + i * 256;   // 0..2559
            uint32_t dst;
            const __nv_bfloat16* src;
            if (c < 1024) {
                int r = c >> 3, ch = c & 7;
                dst = su + swz((uint32_t)(r * 128 + ch * 16));
                src = Ah + (size_t)r * DD + k0 + ch * 8;
            } else if (c < 1792) {
                int cc = c - 1024, r = cc >> 3, ch = cc & 7;   // r 0..95
                dst = su + ASZ + swz((uint32_t)(r * 128 + ch * 16));
                src = g_w2h + (size_t)r * DD + k0 + ch * 8;
            } else {
                int cc = c - 1792, r = cc >> 3, ch = cc & 7;
                dst = su + ASZ + BSZ + swz((uint32_t)(r * 128 + ch * 16));
                src = g_w2l + (size_t)r * DD + k0 + ch * 8;
            }
            cp16(dst, src);
        }
    };

    ldstage(0, 0);
    CP_COMMIT();

    const uint32_t idesc = (1u << 4) | (1u << 7) | (1u << 10) |
                           ((uint32_t)(NTB / 8) << 17) | (8u << 24);

    for (int kb = 0; kb < NKB; kb++) {
        const int st = kb & 1;
        if (kb + 1 < NKB) ldstage(st ^ 1, kb + 1);
        CP_COMMIT();
        asm volatile("cp.async.wait_group 1;" ::: "memory");
        __syncthreads();
        if (wid == 0) {
            asm volatile("fence.proxy.async.shared::cta;" ::: "memory");
            if (elect1()) {
                const uint32_t su = sb + st * STAGE;
                uint64_t ah = mkdesc(su);
                uint64_t bh = mkdesc(su + ASZ);
                uint64_t bl = mkdesc(su + ASZ + BSZ);
#pragma unroll
                for (int s4 = 0; s4 < 4; s4++) {
                    uint64_t o = 2 * s4;
                    mma_bf16_ss(tmem, ah + o, bh + o, idesc, !(kb == 0 && s4 == 0));
                    mma_bf16_ss(tmem, ah + o, bl + o, idesc, true);
                }
                asm volatile(
                    "tcgen05.commit.cta_group::1.mbarrier::arrive::one.shared::cluster.b64 [%0];"
                    :: "r"(mbar) : "memory");
            }
        }
        mbar_wait(mbar, (uint32_t)(kb & 1));
    }

    asm volatile("tcgen05.fence::after_thread_sync;" ::: "memory");
    __syncthreads();

    float* sh = (float*)dynsm;  // [128][81]
    if (wid < 4) {
        float v[VV];
        {
            uint32_t r[32];
            LDTM_X32(r, tmem);
            TM_WAIT_LD();
#pragma unroll
            for (int j = 0; j < 32; j++) v[j] = __uint_as_float(r[j]);
        }
        {
            uint32_t r[32];
            LDTM_X32(r, tmem + 32);
            TM_WAIT_LD();
#pragma unroll
            for (int j = 0; j < 32; j++) v[32 + j] = __uint_as_float(r[j]);
        }
        {
            uint32_t r[16];
            LDTM_X16(r, tmem + 64);
            TM_WAIT_LD();
#pragma unroll
            for (int j = 0; j < 16; j++) v[64 + j] = __uint_as_float(r[j]);
        }
        asm volatile("tcgen05.fence::before_thread_sync;" ::: "memory");
        float mx = -1e30f;
#pragma unroll
        for (int j = 0; j < VV; j++) { v[j] += b2[j]; mx = fmaxf(mx, v[j]); }
        float sum = 0.f;
#pragma unroll
        for (int j = 0; j < VV; j++) sum += expf(v[j] - mx);
        const float lse = mx + logf(sum);
        const int row = wid * 32 + lid;
#pragma unroll
        for (int j = 0; j < VV; j++) sh[row * 81 + j] = v[j] - lse;
    }
    __syncthreads();
#pragma unroll 4
    for (int i = 0; i < 40; i++) {
        int idx = tid + i * 256;
        int rr = idx / 80, cc = idx - rr * 80;
        int t = m0 + rr;
        if (t < TT) g_lp[((size_t)b * TT + t) * VV + cc] = sh[rr * 81 + cc];
    }
    __syncthreads();
    if (wid == 0)
        asm volatile("tcgen05.dealloc.cta_group::1.sync.aligned.b32 %0, %1;"
                     :: "r"(tmem), "r"(128u));

#else  // SIMT fallback (compile-only)
    const int r = m0 + (tid & 127);
    if (tid < 128) {
        float v[VV];
        for (int j = 0; j < VV; j++) v[j] = b2[j];
        const __nv_bfloat16* hh = g_hb + ((size_t)b * TP + r) * DD;
        for (int k = 0; k < DD; k++) {
            float hv = __bfloat162float(hh[k]);
            for (int j = 0; j < VV; j++)
                v[j] = fmaf(hv, __bfloat162float(g_w2h[(size_t)j * DD + k]) +
                                 __bfloat162float(g_w2l[(size_t)j * DD + k]), v[j]);
        }
        float mx = -1e30f;
        for (int j = 0; j < VV; j++) mx = fmaxf(mx, v[j]);
        float sum = 0.f;
        for (int j = 0; j < VV; j++) sum += expf(v[j] - mx);
        float lse = mx + logf(sum);
        if (r < TT)
            for (int j = 0; j < VV; j++)
                g_lp[((size_t)b * TT + r) * VV + j] = v[j] - lse;
    }
#endif
}

// ---------------- CTC DP: 2 states/thread, register-carried, 224 threads -----
// Thread i owns states s0=2i (blank) and s1=2i+1 (label). Even states never
// skip, so v0 is a 2-term lse. s1-1=s0 and s1-2=s0-1, so the only cross-thread
// read per step is ONE shared scalar (neighbor's v1). Physical shared index =
// state + 2 (front pad, never written -> NEGV).
__global__ __launch_bounds__(224) void k_ctc(const int* __restrict__ tgt,
                                             const int* __restrict__ dlen,
                                             const int* __restrict__ tlen) {
    const int b = blockIdx.x;
    const int L = tlen[b];
    const int len = dlen[b];
    const int i = threadIdx.x;
    const int s0 = 2 * i;

    __shared__ float A[2][452];   // phys = state + 2; states up to 447 covered
    __shared__ int lab[224];

    const float* lpb = g_lp + (size_t)b * TT * VV;

    const int ti = (i < LMAX) ? i : LMAX - 1;
    const int lbl1 = tgt[b * LMAX + ti];
    lab[i] = lbl1;
    for (int j = i; j < 452; j += 224) {
        A[0][j] = NEGV;
        A[1][j] = NEGV;
    }
    __syncthreads();

    const bool sk1 = (i >= 1) && (lbl1 != lab[i - 1]);

    // t = 0 init (registers + shared row 0)
    float r0 = NEGV, r1 = NEGV;
    if (i == 0) {
        r0 = lpb[BLANK];
        r1 = lpb[lbl1];
    }
    A[0][s0 + 2] = r0;
    A[0][s0 + 3] = r1;

    // 2-deep emission prefetch (blank + own label)
    int t1c = (1 < len) ? 1 : len - 1;
    int t2c = (2 < len) ? 2 : len - 1;
    float e0A = lpb[(size_t)t1c * VV + BLANK];
    float e1A = lpb[(size_t)t1c * VV + lbl1];
    float e0B = lpb[(size_t)t2c * VV + BLANK];
    float e1B = lpb[(size_t)t2c * VV + lbl1];
    __syncthreads();

    for (int t = 1; t < len; t++) {
        const int cur = t & 1, prev = cur ^ 1;
        float e0 = e0A, e1 = e1A;
        e0A = e0B; e1A = e1B;
        int tn = (t + 2 < len) ? t + 2 : len - 1;
        e0B = lpb[(size_t)tn * VV + BLANK];
        e1B = lpb[(size_t)tn * VV + lbl1];

        // neighbor's previous v1 (state s0-1) — the single cross-thread value
        float nb = A[prev][s0 + 1];

        // v0 (blank state): lse2(r0, nb) + e0
        float mx0 = fmaxf(r0, nb);
        float mn0 = fminf(r0, nb);
        float v0 = mx0 + __logf(1.f + __expf(mn0 - mx0)) + e0;

        // v1 (label state): lse3(r1, r0, sk1 ? nb : NEGV) + e1
        float c  = sk1 ? nb : NEGV;
        float mx = fmaxf(r1, fmaxf(r0, c));
        float mn = fminf(r1, fminf(r0, c));
        float md = fmaxf(fminf(r1, r0), fminf(fmaxf(r1, r0), c));
        float v1 = mx + __logf(1.f + __expf(md - mx) + __expf(mn - mx)) + e1;

        r0 = v0; r1 = v1;
        *reinterpret_cast<float2*>(&A[cur][s0 + 2]) = make_float2(v0, v1);
        __syncthreads();
    }

    if (i == 0) {
        const int f = (len - 1) & 1;
        float l1 = A[f][2 * L - 1 + 2];
        float l2 = A[f][2 * L + 2];
        float m = fmaxf(l1, l2);
        float last = m + logf(expf(l1 - m) + expf(l2 - m));
        float nll = (last > 0.5f * NEGV) ? -last : 0.f;
        g_loss[b] = nll / (float)len;
    }
}

__global__ __launch_bounds__(32) void k_reduce(float* __restrict__ out) {
    float v = g_loss[threadIdx.x];
#pragma unroll
    for (int o = 16; o > 0; o >>= 1) v += __shfl_xor_sync(0xffffffffu, v, o);
    if (threadIdx.x == 0) out[0] = v * (1.0f / BB);
}

// ---------------------------------------------------------------------------
extern "C" void kernel_launch(void* const* d_in, const int* in_sizes, int n_in,
                              void* d_out, int out_size) {
    const float* dec  = (const float*)d_in[0];
    const int*   tgt  = (const int*)d_in[1];
    const int*   dlen = (const int*)d_in[2];
    const int*   tlen = (const int*)d_in[3];
    const float* W1   = (const float*)d_in[4];
    const float* b1   = (const float*)d_in[5];
    const float* W2   = (const float*)d_in[6];
    const float* b2   = (const float*)d_in[7];
    float* out = (float*)d_out;

    const int SMEM1 = 197632;  // pad + 2 x 98304 stages (epilogue 133.6KB reuses)
    const int SMEM2 = 82944;   // pad + 2 x 40960 stages -> 2 CTAs/SM
    cudaFuncSetAttribute(k_gemm1, cudaFuncAttributeMaxDynamicSharedMemorySize, SMEM1);
    cudaFuncSetAttribute(k_gemm2, cudaFuncAttributeMaxDynamicSharedMemorySize, SMEM2);

    k_prep_dec<<<dim3(TP / 32, DD / 32, BB), dim3(32, 8)>>>(dec);
    k_prep_w1<<<dim3(DD / 32, DD / 32), dim3(32, 8)>>>(W1);
    k_prep_w2<<<(NTB * DD + 255) / 256, 256>>>(W2);

    k_gemm1<<<dim3(TP / 256, DD / 256, BB), 256, SMEM1>>>(dec, W1, b1);
    k_gemm2<<<dim3(TP / 128, BB), 256, SMEM2>>>(b2);

    k_ctc<<<BB, 224>>>(tgt, dlen, tlen);
    k_reduce<<<1, 32>>>(out);
}